// round 7
// baseline (speedup 1.0000x reference)
#include <cuda_runtime.h>
#include <math.h>

// ---------------- problem constants ----------------
#define Hh 256
#define Bsz 128
#define Asz 24
#define Nn (Bsz*Asz)          // 3072 nodes
#define Ee (Bsz*Asz*Asz)      // 73728 edges
#define MAXA 103
#define TIMED 256
#define TEXTD 128
#define NFREQ 10
#define NLAYERS 4
#define EDGE_IN (2*Hh+9+60)   // 581
#define LD_PAD 80             // 9 lat + 60 demb, padded to 80 (5 x BK16)

#define O_TYPES 0
#define O_LATT  (Nn*MAXA)
#define O_COORD (O_LATT + Bsz*9)
#define O_NF    (O_COORD + Nn*3)

typedef unsigned long long ull;

// ---------------- scratch ----------------
__device__ float g_nf[Nn*Hh];
__device__ float g_PQ[Nn*2*Hh];
__device__ float g_no1[Nn*Hh];
__device__ float g_agg[Nn*Hh];
__device__ float g_ef1[(size_t)Ee*Hh];
__device__ float g_latdemb[(size_t)Ee*LD_PAD];
__device__ float g_w1r[Hh*LD_PAD];
__device__ float g_wPQ[2*Hh*Hh];
__device__ float g_cond[Bsz*2*Hh];
__device__ float g_latips[Bsz*9];
__device__ float g_gfeat[Bsz*Hh];
__device__ float g_lattmp[Bsz*9];

__device__ __forceinline__ float siluf(float x){
    float h = 0.5f*x, t;
    asm("tanh.approx.f32 %0, %1;" : "=f"(t) : "f"(h));
    return h*(1.f+t);
}
__device__ __forceinline__ ull pack2(float x, float y){
    ull r; asm("mov.b64 %0, {%1, %2};" : "=l"(r) : "f"(x), "f"(y)); return r;
}
__device__ __forceinline__ void unpack2(ull v, float &x, float &y){
    asm("mov.b64 {%0, %1}, %2;" : "=f"(x), "=f"(y) : "l"(v));
}
__device__ __forceinline__ void fma2(ull &d, ull a, ull b){
    asm("fma.rn.f32x2 %0, %1, %2, %0;" : "+l"(d) : "l"(a), "l"(b));
}

// smem sizes (dynamic)
#define SMEM_BIG  ((2*16*2*128 + 2*16*256)*4)   // 65536
#define SMEM_E2   ((2*16*2*96  + 2*16*256)*4)   // 57344

// =====================================================================
// big_gemm: BM=128, BN=256, BK=16, TM=8, TN=16, 256 thr, f32x2, dup-A smem
// C[:, n0:n0+256] = epi(A @ W[n0:n0+256,:]^T)
// =====================================================================
template<bool CONCAT,bool ACT,bool RESID,bool BIAS>
__global__ __launch_bounds__(256) void big_gemm(
    const float* __restrict__ A, const float* __restrict__ A2, int K1,
    const float* __restrict__ W, int ldw,
    const float* __restrict__ bias, const float* __restrict__ resid,
    float* __restrict__ C, int ldc, int K)
{
    const int BM=128,BN=256,BK=16,NT=256;
    extern __shared__ float sm[];
    float* As_ = sm;                    // [2][BK][2*BM]
    float* Bs_ = sm + 2*BK*2*BM;        // [2][BK][BN]
    const int tid=threadIdx.x;
    const int tc=tid&15, tr=tid>>4;
    const int m0=blockIdx.y*BM, n0=blockIdx.x*BN;

    ull acc[8][8];
    #pragma unroll
    for(int i=0;i<8;i++)
        #pragma unroll
        for(int j=0;j<8;j++) acc[i][j]=0ULL;

    float4 fa[2], fb[4];

    auto loadA=[&](int k0){
        #pragma unroll
        for(int u=0;u<2;u++){
            int s=tid+u*NT; int mm=s>>2, kq=(s&3)<<2;
            if(CONCAT){
                int gk=k0+kq;
                const float* src = (gk<K1)? A+(size_t)(m0+mm)*K1+gk
                                          : A2+(size_t)(m0+mm)*K1+(gk-K1);
                fa[u]=*(const float4*)src;
            } else fa[u]=*(const float4*)(A+(size_t)(m0+mm)*K+k0+kq);
        }
    };
    auto loadB=[&](int k0){
        #pragma unroll
        for(int u=0;u<4;u++){
            int s=tid+u*NT; int nn=s>>2, kq=(s&3)<<2;
            fb[u]=*(const float4*)(W+(size_t)(n0+nn)*ldw+k0+kq);
        }
    };
    auto storeA=[&](int b){
        #pragma unroll
        for(int u=0;u<2;u++){
            int s=tid+u*NT; int mm=s>>2, kq=(s&3)<<2;
            float v[4]={fa[u].x,fa[u].y,fa[u].z,fa[u].w};
            #pragma unroll
            for(int j=0;j<4;j++)
                *(ull*)&As_[(size_t)(b*BK+kq+j)*(2*BM) + 2*mm] = pack2(v[j],v[j]);
        }
    };
    auto storeB=[&](int b){
        #pragma unroll
        for(int u=0;u<4;u++){
            int s=tid+u*NT; int nn=s>>2, kq=(s&3)<<2;
            Bs_[(size_t)(b*BK+kq+0)*BN+nn]=fb[u].x;
            Bs_[(size_t)(b*BK+kq+1)*BN+nn]=fb[u].y;
            Bs_[(size_t)(b*BK+kq+2)*BN+nn]=fb[u].z;
            Bs_[(size_t)(b*BK+kq+3)*BN+nn]=fb[u].w;
        }
    };

    loadA(0); loadB(0); storeA(0); storeB(0); __syncthreads();
    const int ntile=K/BK;
    for(int t=0;t<ntile;t++){
        int cur=t&1;
        if(t+1<ntile){ loadA((t+1)*BK); loadB((t+1)*BK); }
        #pragma unroll
        for(int kk=0;kk<BK;kk++){
            ull av[8], bv[8];
            const float* ar = &As_[(size_t)(cur*BK+kk)*(2*BM) + 2*(tr*8)];
            const float* br = &Bs_[(size_t)(cur*BK+kk)*BN + tc*16];
            #pragma unroll
            for(int p=0;p<4;p++){ ulonglong2 t2=*(const ulonglong2*)(ar+4*p); av[2*p]=t2.x; av[2*p+1]=t2.y; }
            #pragma unroll
            for(int q=0;q<4;q++){ ulonglong2 t2=*(const ulonglong2*)(br+4*q); bv[2*q]=t2.x; bv[2*q+1]=t2.y; }
            #pragma unroll
            for(int i=0;i<8;i++)
                #pragma unroll
                for(int j=0;j<8;j++) fma2(acc[i][j],av[i],bv[j]);
        }
        if(t+1<ntile){ int nb=cur^1; storeA(nb); storeB(nb); __syncthreads(); }
    }

    const int col0 = tc*16;
    float4 bb[4];
    if(BIAS){
        #pragma unroll
        for(int q=0;q<4;q++) bb[q]=*(const float4*)(bias+n0+col0+4*q);
    }
    #pragma unroll
    for(int i=0;i<8;i++){
        int gm=m0+tr*8+i;
        float v[16];
        #pragma unroll
        for(int j=0;j<8;j++) unpack2(acc[i][j], v[2*j], v[2*j+1]);
        if(BIAS){
            #pragma unroll
            for(int q=0;q<4;q++){ v[4*q]+=bb[q].x; v[4*q+1]+=bb[q].y; v[4*q+2]+=bb[q].z; v[4*q+3]+=bb[q].w; }
        }
        if(ACT){
            #pragma unroll
            for(int k=0;k<16;k++) v[k]=siluf(v[k]);
        }
        if(RESID){
            #pragma unroll
            for(int q=0;q<4;q++){
                float4 r4=*(const float4*)(resid+(size_t)gm*ldc+n0+col0+4*q);
                v[4*q]+=r4.x; v[4*q+1]+=r4.y; v[4*q+2]+=r4.z; v[4*q+3]+=r4.w;
            }
        }
        #pragma unroll
        for(int q=0;q<4;q++)
            *(float4*)(C+(size_t)gm*ldc+n0+col0+4*q)=make_float4(v[4*q],v[4*q+1],v[4*q+2],v[4*q+3]);
    }
}

// =====================================================================
// edge1: ef1 = silu(latdemb @ W1r^T + P[e0] + Q[e1] + b1)    K=80, BN=256
// =====================================================================
__global__ __launch_bounds__(256) void edge1_gemm(
    const float* __restrict__ A,    // [Ee][80]
    const float* __restrict__ W,    // [256][80]
    const float* __restrict__ bias,
    const float* __restrict__ PQ,   // [Nn][512]
    float* __restrict__ C)          // [Ee][256]
{
    const int BM=128,BN=256,BK=16,NT=256,K=LD_PAD;
    extern __shared__ float sm[];
    float* As_ = sm;
    float* Bs_ = sm + 2*BK*2*BM;
    const int tid=threadIdx.x;
    const int tc=tid&15, tr=tid>>4;
    const int m0=blockIdx.x*BM;

    ull acc[8][8];
    #pragma unroll
    for(int i=0;i<8;i++)
        #pragma unroll
        for(int j=0;j<8;j++) acc[i][j]=0ULL;

    float4 fa[2], fb[4];
    auto loadA=[&](int k0){
        #pragma unroll
        for(int u=0;u<2;u++){
            int s=tid+u*NT; int mm=s>>2, kq=(s&3)<<2;
            fa[u]=*(const float4*)(A+(size_t)(m0+mm)*K+k0+kq);
        }
    };
    auto loadB=[&](int k0){
        #pragma unroll
        for(int u=0;u<4;u++){
            int s=tid+u*NT; int nn=s>>2, kq=(s&3)<<2;
            fb[u]=*(const float4*)(W+(size_t)nn*K+k0+kq);
        }
    };
    auto storeA=[&](int b){
        #pragma unroll
        for(int u=0;u<2;u++){
            int s=tid+u*NT; int mm=s>>2, kq=(s&3)<<2;
            float v[4]={fa[u].x,fa[u].y,fa[u].z,fa[u].w};
            #pragma unroll
            for(int j=0;j<4;j++)
                *(ull*)&As_[(size_t)(b*BK+kq+j)*(2*BM)+2*mm]=pack2(v[j],v[j]);
        }
    };
    auto storeB=[&](int b){
        #pragma unroll
        for(int u=0;u<4;u++){
            int s=tid+u*NT; int nn=s>>2, kq=(s&3)<<2;
            Bs_[(size_t)(b*BK+kq+0)*BN+nn]=fb[u].x;
            Bs_[(size_t)(b*BK+kq+1)*BN+nn]=fb[u].y;
            Bs_[(size_t)(b*BK+kq+2)*BN+nn]=fb[u].z;
            Bs_[(size_t)(b*BK+kq+3)*BN+nn]=fb[u].w;
        }
    };

    loadA(0); loadB(0); storeA(0); storeB(0); __syncthreads();
    const int ntile=K/BK; // 5
    for(int t=0;t<ntile;t++){
        int cur=t&1;
        if(t+1<ntile){ loadA((t+1)*BK); loadB((t+1)*BK); }
        #pragma unroll
        for(int kk=0;kk<BK;kk++){
            ull av[8], bv[8];
            const float* ar=&As_[(size_t)(cur*BK+kk)*(2*BM)+2*(tr*8)];
            const float* br=&Bs_[(size_t)(cur*BK+kk)*BN+tc*16];
            #pragma unroll
            for(int p=0;p<4;p++){ ulonglong2 t2=*(const ulonglong2*)(ar+4*p); av[2*p]=t2.x; av[2*p+1]=t2.y; }
            #pragma unroll
            for(int q=0;q<4;q++){ ulonglong2 t2=*(const ulonglong2*)(br+4*q); bv[2*q]=t2.x; bv[2*q+1]=t2.y; }
            #pragma unroll
            for(int i=0;i<8;i++)
                #pragma unroll
                for(int j=0;j<8;j++) fma2(acc[i][j],av[i],bv[j]);
        }
        if(t+1<ntile){ int nb=cur^1; storeA(nb); storeB(nb); __syncthreads(); }
    }

    const int col0=tc*16;
    float4 bb[4];
    #pragma unroll
    for(int q=0;q<4;q++) bb[q]=*(const float4*)(bias+col0+4*q);
    #pragma unroll
    for(int i=0;i<8;i++){
        int gm=m0+tr*8+i;
        int b=gm/(Asz*Asz), w=gm%(Asz*Asz);
        int e0=b*Asz+w/Asz, e1=b*Asz+w%Asz;
        const float* pp=PQ+(size_t)e0*(2*Hh)+col0;
        const float* qq=PQ+(size_t)e1*(2*Hh)+Hh+col0;
        float v[16];
        #pragma unroll
        for(int j=0;j<8;j++) unpack2(acc[i][j], v[2*j], v[2*j+1]);
        #pragma unroll
        for(int q=0;q<4;q++){
            float4 p4=*(const float4*)(pp+4*q);
            float4 q4=*(const float4*)(qq+4*q);
            v[4*q]  =siluf(v[4*q]  +bb[q].x+p4.x+q4.x);
            v[4*q+1]=siluf(v[4*q+1]+bb[q].y+p4.y+q4.y);
            v[4*q+2]=siluf(v[4*q+2]+bb[q].z+p4.z+q4.z);
            v[4*q+3]=siluf(v[4*q+3]+bb[q].w+p4.w+q4.w);
        }
        #pragma unroll
        for(int q=0;q<4;q++)
            *(float4*)(C+(size_t)gm*Hh+col0+4*q)=make_float4(v[4*q],v[4*q+1],v[4*q+2],v[4*q+3]);
    }
}

// =====================================================================
// edge2: agg[n] = mean_{24 edges} silu(ef1 @ W2^T + b2)
// BM=96 (=4 nodes), TM=6, BN=256, BK=16. In-block reduction, no atomics.
// =====================================================================
__global__ __launch_bounds__(256) void edge2_gemm(
    const float* __restrict__ A,    // ef1 [Ee][256]
    const float* __restrict__ W,    // [256][256]
    const float* __restrict__ bias,
    float* __restrict__ agg)        // [Nn][256]
{
    const int BM=96,BN=256,BK=16,NT=256,K=Hh;
    extern __shared__ float sm[];
    float* As_ = sm;                    // [2][BK][2*BM] = 6144 floats
    float* Bs_ = sm + 2*BK*2*BM;        // [2][BK][BN]  = 8192 floats
    float* red = Bs_;                   // alias after mainloop (4096 floats)
    const int tid=threadIdx.x;
    const int tc=tid&15, tr=tid>>4;
    const int m0=blockIdx.x*BM;

    ull acc[6][8];
    #pragma unroll
    for(int i=0;i<6;i++)
        #pragma unroll
        for(int j=0;j<8;j++) acc[i][j]=0ULL;

    float4 fa[2], fb[4];
    auto loadA=[&](int k0){
        #pragma unroll
        for(int u=0;u<2;u++){
            int s=tid+u*NT;
            if(s<384){ int mm=s>>2, kq=(s&3)<<2;
                fa[u]=*(const float4*)(A+(size_t)(m0+mm)*K+k0+kq); }
        }
    };
    auto loadB=[&](int k0){
        #pragma unroll
        for(int u=0;u<4;u++){
            int s=tid+u*NT; int nn=s>>2, kq=(s&3)<<2;
            fb[u]=*(const float4*)(W+(size_t)nn*K+k0+kq);
        }
    };
    auto storeA=[&](int b){
        #pragma unroll
        for(int u=0;u<2;u++){
            int s=tid+u*NT;
            if(s<384){ int mm=s>>2, kq=(s&3)<<2;
                float v[4]={fa[u].x,fa[u].y,fa[u].z,fa[u].w};
                #pragma unroll
                for(int j=0;j<4;j++)
                    *(ull*)&As_[(size_t)(b*BK+kq+j)*(2*BM)+2*mm]=pack2(v[j],v[j]);
            }
        }
    };
    auto storeB=[&](int b){
        #pragma unroll
        for(int u=0;u<4;u++){
            int s=tid+u*NT; int nn=s>>2, kq=(s&3)<<2;
            Bs_[(size_t)(b*BK+kq+0)*BN+nn]=fb[u].x;
            Bs_[(size_t)(b*BK+kq+1)*BN+nn]=fb[u].y;
            Bs_[(size_t)(b*BK+kq+2)*BN+nn]=fb[u].z;
            Bs_[(size_t)(b*BK+kq+3)*BN+nn]=fb[u].w;
        }
    };

    loadA(0); loadB(0); storeA(0); storeB(0); __syncthreads();
    const int ntile=K/BK; // 16
    for(int t=0;t<ntile;t++){
        int cur=t&1;
        if(t+1<ntile){ loadA((t+1)*BK); loadB((t+1)*BK); }
        #pragma unroll
        for(int kk=0;kk<BK;kk++){
            ull av[6], bv[8];
            const float* ar=&As_[(size_t)(cur*BK+kk)*(2*BM)+2*(tr*6)];
            const float* br=&Bs_[(size_t)(cur*BK+kk)*BN+tc*16];
            #pragma unroll
            for(int p=0;p<3;p++){ ulonglong2 t2=*(const ulonglong2*)(ar+4*p); av[2*p]=t2.x; av[2*p+1]=t2.y; }
            #pragma unroll
            for(int q=0;q<4;q++){ ulonglong2 t2=*(const ulonglong2*)(br+4*q); bv[2*q]=t2.x; bv[2*q+1]=t2.y; }
            #pragma unroll
            for(int i=0;i<6;i++)
                #pragma unroll
                for(int j=0;j<8;j++) fma2(acc[i][j],av[i],bv[j]);
        }
        if(t+1<ntile){ int nb=cur^1; storeA(nb); storeB(nb); __syncthreads(); }
    }

    // silu + per-thread partial sums (6 rows, all in one node since tr*6..tr*6+5 stays inside 24)
    const int col0=tc*16;
    float4 bb[4];
    #pragma unroll
    for(int q=0;q<4;q++) bb[q]=*(const float4*)(bias+col0+4*q);
    float cs[16];
    #pragma unroll
    for(int k=0;k<16;k++) cs[k]=0.f;
    #pragma unroll
    for(int i=0;i<6;i++){
        float v[16];
        #pragma unroll
        for(int j=0;j<8;j++) unpack2(acc[i][j], v[2*j], v[2*j+1]);
        #pragma unroll
        for(int q=0;q<4;q++){
            cs[4*q]  +=siluf(v[4*q]  +bb[q].x);
            cs[4*q+1]+=siluf(v[4*q+1]+bb[q].y);
            cs[4*q+2]+=siluf(v[4*q+2]+bb[q].z);
            cs[4*q+3]+=siluf(v[4*q+3]+bb[q].w);
        }
    }
    __syncthreads();   // done reading Bs; reuse as red[16][256]
    #pragma unroll
    for(int q=0;q<4;q++)
        *(float4*)&red[(size_t)tr*BN+col0+4*q]=make_float4(cs[4*q],cs[4*q+1],cs[4*q+2],cs[4*q+3]);
    __syncthreads();
    if((tr&3)==0){
        int node = blockIdx.x*4 + (tr>>2);
        #pragma unroll
        for(int q=0;q<4;q++){
            float4 r0=*(const float4*)&red[(size_t)(tr+0)*BN+col0+4*q];
            float4 r1=*(const float4*)&red[(size_t)(tr+1)*BN+col0+4*q];
            float4 r2=*(const float4*)&red[(size_t)(tr+2)*BN+col0+4*q];
            float4 r3=*(const float4*)&red[(size_t)(tr+3)*BN+col0+4*q];
            float4 o=make_float4((r0.x+r1.x+r2.x+r3.x)*(1.f/24.f),
                                 (r0.y+r1.y+r2.y+r3.y)*(1.f/24.f),
                                 (r0.z+r1.z+r2.z+r3.z)*(1.f/24.f),
                                 (r0.w+r1.w+r2.w+r3.w)*(1.f/24.f));
            *(float4*)(agg+(size_t)node*Hh+col0+4*q)=o;
        }
    }
}

// ===== fused: y = nf@w_proj^T + b; nf += silu(LN(y)*fg+fb * FiLM) =====
__global__ __launch_bounds__(256) void projfilm(
    const float* __restrict__ wproj, const float* __restrict__ bproj,
    const float* __restrict__ cond,
    const float* __restrict__ fg, const float* __restrict__ fb,
    float* nf)
{
    const int BM=32,BN=256,BK=8,TM=4,TN=8,NT=256,K=Hh;
    __shared__ __align__(16) float As[2][BK][BM];
    __shared__ __align__(16) float Bs[2][BK][BN];
    const int tid=threadIdx.x;
    const int tc=tid%32, tr=tid/32;
    const int m0=blockIdx.x*BM;

    ull acc[TM][TN/2];
    #pragma unroll
    for(int i=0;i<TM;i++)
        #pragma unroll
        for(int j=0;j<TN/2;j++) acc[i][j]=0ULL;

    float ra[1], rb[8];
    { int i=tid; ra[0]=nf[(size_t)(m0+i/BK)*K + i%BK]; }
    #pragma unroll
    for(int u=0;u<8;u++){int i=tid+u*NT; rb[u]=wproj[(size_t)(i/BK)*K + i%BK];}
    { int i=tid; As[0][i%BK][i/BK]=ra[0]; }
    #pragma unroll
    for(int u=0;u<8;u++){int i=tid+u*NT; Bs[0][i%BK][i/BK]=rb[u];}
    __syncthreads();

    const int ntile=K/BK;
    for(int t=0;t<ntile;t++){
        int cur=t&1;
        if(t+1<ntile){
            int k0=(t+1)*BK;
            { int i=tid; ra[0]=nf[(size_t)(m0+i/BK)*K + k0 + i%BK]; }
            #pragma unroll
            for(int u=0;u<8;u++){int i=tid+u*NT; rb[u]=wproj[(size_t)(i/BK)*K + k0 + i%BK];}
        }
        #pragma unroll
        for(int kk=0;kk<BK;kk++){
            ull av[TM], bv[TN/2];
            #pragma unroll
            for(int i=0;i<TM;i++){ float a=As[cur][kk][tr*TM+i]; av[i]=pack2(a,a); }
            #pragma unroll
            for(int j=0;j<TN/2;j++) bv[j]=*reinterpret_cast<const ull*>(&Bs[cur][kk][tc*TN+2*j]);
            #pragma unroll
            for(int i=0;i<TM;i++)
                #pragma unroll
                for(int j=0;j<TN/2;j++) fma2(acc[i][j],av[i],bv[j]);
        }
        if(t+1<ntile){
            int nb=cur^1;
            { int i=tid; As[nb][i%BK][i/BK]=ra[0]; }
            #pragma unroll
            for(int u=0;u<8;u++){int i=tid+u*NT; Bs[nb][i%BK][i/BK]=rb[u];}
            __syncthreads();
        }
    }

    const int col0 = tc*TN;
    #pragma unroll
    for(int i=0;i<TM;i++){
        int gm = m0 + tr*TM + i;
        int g  = gm/Asz;
        float v[8];
        #pragma unroll
        for(int j=0;j<TN/2;j++) unpack2(acc[i][j], v[2*j], v[2*j+1]);
        #pragma unroll
        for(int jj=0;jj<8;jj++) v[jj] += bproj[col0+jj];
        float s=0.f;
        #pragma unroll
        for(int jj=0;jj<8;jj++) s+=v[jj];
        #pragma unroll
        for(int o=16;o>0;o>>=1) s += __shfl_xor_sync(0xffffffffu, s, o);
        float mu = s*(1.0f/256.0f);
        float ss=0.f;
        #pragma unroll
        for(int jj=0;jj<8;jj++){ v[jj]-=mu; ss+=v[jj]*v[jj]; }
        #pragma unroll
        for(int o=16;o>0;o>>=1) ss += __shfl_xor_sync(0xffffffffu, ss, o);
        float rstd = rsqrtf(ss*(1.0f/256.0f) + 1e-5f);
        #pragma unroll
        for(int jj=0;jj<8;jj++){
            int col = col0+jj;
            float y  = v[jj]*rstd*fg[col] + fb[col];
            float sc = cond[(size_t)g*(2*Hh)+col];
            float sh = cond[(size_t)g*(2*Hh)+Hh+col];
            nf[(size_t)gm*Hh+col] += siluf(y*sc + sh);
        }
    }
}

// ================= guarded GEMM (cold paths) ========
template<int BM,int BN,int BK,int TM,int TN,int AMODE>
__global__ void gemm_k(
    int M, int Nout, int K,
    const float* __restrict__ A, int lda,
    const float* __restrict__ A2, int K1, int lda2,
    const float* __restrict__ W, int ldw,
    const float* __restrict__ bias,
    float* __restrict__ C, int ldc,
    int act)
{
    __shared__ float As[BK][BM];
    __shared__ float Bs[BK][BN];
    const int NT = (BM/TM)*(BN/TN);
    const int tid = threadIdx.x;
    const int tc  = tid % (BN/TN);
    const int tr  = tid / (BN/TN);
    const int m0  = blockIdx.y * BM;
    const int n0  = blockIdx.x * BN;

    float acc[TM][TN];
    #pragma unroll
    for (int i=0;i<TM;i++)
        #pragma unroll
        for (int j=0;j<TN;j++) acc[i][j]=0.f;

    for (int k0 = 0; k0 < K; k0 += BK) {
        for (int i = tid; i < BM*BK; i += NT) {
            int mm = i / BK, kk = i % BK;
            int gm = m0 + mm, gk = k0 + kk;
            float v = 0.f;
            if (gm < M && gk < K) {
                if (AMODE == 0) v = A[(size_t)gm*lda + gk];
                else v = (gk < K1) ? A[(size_t)gm*lda + gk] : A2[(size_t)gm*lda2 + (gk-K1)];
            }
            As[kk][mm] = v;
        }
        for (int i = tid; i < BN*BK; i += NT) {
            int nn = i / BK, kk = i % BK;
            int gn = n0 + nn, gk = k0 + kk;
            Bs[kk][nn] = (gn < Nout && gk < K) ? W[(size_t)gn*ldw + gk] : 0.f;
        }
        __syncthreads();
        #pragma unroll
        for (int kk = 0; kk < BK; kk++) {
            float a[TM], b[TN];
            #pragma unroll
            for (int i=0;i<TM;i++) a[i] = As[kk][tr*TM+i];
            #pragma unroll
            for (int j=0;j<TN;j++) b[j] = Bs[kk][tc*TN+j];
            #pragma unroll
            for (int i=0;i<TM;i++)
                #pragma unroll
                for (int j=0;j<TN;j++) acc[i][j] += a[i]*b[j];
        }
        __syncthreads();
    }

    #pragma unroll
    for (int i=0;i<TM;i++) {
        int gm = m0 + tr*TM + i;
        if (gm >= M) continue;
        #pragma unroll
        for (int j=0;j<TN;j++) {
            int gn = n0 + tc*TN + j;
            if (gn >= Nout) continue;
            float v = acc[i][j];
            if (bias) v += bias[gn];
            if (act)  v = siluf(v);
            C[(size_t)gm*ldc + gn] = v;
        }
    }
}

// ---------------- small kernels ----------------
__global__ void copy_f(const float* __restrict__ a, float* __restrict__ b, int n){
    int i=blockIdx.x*blockDim.x+threadIdx.x; if(i<n) b[i]=a[i];
}
__global__ void latips_kernel(const float* __restrict__ L, float* __restrict__ out){
    int idx = blockIdx.x*blockDim.x+threadIdx.x;
    if (idx >= Bsz*9) return;
    int b = idx/9, r = idx%9, i = r/3, k = r%3;
    out[idx] = L[b*9+i*3+0]*L[b*9+k*3+0] + L[b*9+i*3+1]*L[b*9+k*3+1] + L[b*9+i*3+2]*L[b*9+k*3+2];
}
__global__ void latdemb_kernel(const float* __restrict__ fc, const float* __restrict__ latips,
                               float* __restrict__ out){
    int e = blockIdx.x*blockDim.x+threadIdx.x;
    if (e >= Ee) return;
    int b = e/(Asz*Asz), w = e%(Asz*Asz);
    int a = b*Asz + w/Asz, c = b*Asz + w%Asz;
    float* o = out + (size_t)e*LD_PAD;
    #pragma unroll
    for (int i=0;i<9;i++) o[i] = latips[b*9+i];
    #pragma unroll
    for (int d=0;d<3;d++){
        float df = fc[c*3+d] - fc[a*3+d];
        df -= floorf(df);
        #pragma unroll
        for (int f=0;f<NFREQ;f++){
            float ang = 6.283185307179586f * (float)f * df;
            float sn, cs; sincosf(ang, &sn, &cs);
            o[9 + d*NFREQ + f]      = sn;
            o[9 + 30 + d*NFREQ + f] = cs;
        }
    }
    #pragma unroll
    for (int i=69;i<LD_PAD;i++) o[i]=0.f;
}
__global__ void pack_w1r(const float* __restrict__ ew1, float* __restrict__ w1r){
    int i = blockIdx.x*blockDim.x+threadIdx.x;
    if (i >= Hh*LD_PAD) return;
    int n = i/LD_PAD, k = i%LD_PAD;
    w1r[i] = (k < 69) ? ew1[(size_t)n*EDGE_IN + 2*Hh + k] : 0.f;
}
__global__ void pack_wPQ(const float* __restrict__ ew1, float* __restrict__ wPQ){
    int i = blockIdx.x*blockDim.x+threadIdx.x;
    if (i >= 2*Hh*Hh) return;
    int n = i/Hh, k = i%Hh;
    wPQ[i] = (n < Hh) ? ew1[(size_t)n*EDGE_IN + k] : ew1[(size_t)(n-Hh)*EDGE_IN + Hh + k];
}
__global__ void gfeat2(const float* __restrict__ nf, float* __restrict__ gf){
    int i=blockIdx.x*blockDim.x+threadIdx.x;
    if (i >= Bsz*Hh) return;
    int b=i/Hh, h=i%Hh;
    float s=0.f;
    #pragma unroll
    for(int a=0;a<Asz;a++) s += nf[(size_t)(b*Asz+a)*Hh+h];
    gf[i]=s;
}
__global__ void lattmp_kernel(const float* __restrict__ gf, const float* __restrict__ w_latt,
                              float* __restrict__ lt){
    int idx = blockIdx.x*blockDim.x+threadIdx.x;
    if (idx >= Bsz*9) return;
    int b = idx/9, r = idx%9;
    float s = 0.f;
    for (int k=0;k<Hh;k++) s += gf[b*Hh+k]*w_latt[r*Hh+k];
    lt[idx] = s * (1.f/(float)Asz);
}
__global__ void lattout_kernel(const float* __restrict__ lt, const float* __restrict__ L,
                               float* __restrict__ out){
    int idx = blockIdx.x*blockDim.x+threadIdx.x;
    if (idx >= Bsz*9) return;
    int b = idx/9, r = idx%9, i = r/3, k = r%3;
    float s = 0.f;
    #pragma unroll
    for (int j=0;j<3;j++) s += lt[b*9+i*3+j]*L[b*9+j*3+k];
    out[idx] = s;
}
__global__ void coords_kernel(const float* __restrict__ nf, const float* __restrict__ wc,
                              float* __restrict__ out){
    int idx = blockIdx.x*blockDim.x+threadIdx.x;
    if (idx >= Nn*3) return;
    int n = idx/3, d = idx%3;
    float s = 0.f;
    for (int k=0;k<Hh;k++) s += nf[(size_t)n*Hh+k]*wc[d*Hh+k];
    out[idx] = s;
}

// ---------------- host helpers ----------------
static void gemm_guard(int M,int Nout,int K, const float* A,int lda,
                       const float* W,int ldw, const float* bias,
                       float* C,int ldc,int act){
    dim3 grid((Nout+63)/64, (M+63)/64);
    gemm_k<64,64,16,4,4,0><<<grid,256>>>(M,Nout,K, A,lda, nullptr,0,0,
        W,ldw,bias, C,ldc, act);
}
static void gemm_guard_cat(int M,int Nout,int K1,int K2, const float* A1,const float* A2,
                           const float* W,int ldw,const float* bias,
                           float* C,int ldc,int act){
    dim3 grid((Nout+63)/64, (M+63)/64);
    gemm_k<64,64,16,4,4,1><<<grid,256>>>(M,Nout,K1+K2, A1,K1, A2,K1,K2,
        W,ldw,bias, C,ldc, act);
}

extern "C" void kernel_launch(void* const* d_in, const int* in_sizes, int n_in,
                              void* d_out, int out_size){
    const float* atom_types=(const float*)d_in[0];
    const float* frac      =(const float*)d_in[1];
    const float* lattices  =(const float*)d_in[2];
    const float* t         =(const float*)d_in[3];
    const float* text      =(const float*)d_in[4];
    const float* w_emb     =(const float*)d_in[5];
    const float* b_emb     =(const float*)d_in[6];
    const float* w_cond    =(const float*)d_in[7];
    const float* b_cond    =(const float*)d_in[8];
    const float* w_proj    =(const float*)d_in[9];
    const float* b_proj    =(const float*)d_in[10];
    const float* film_g    =(const float*)d_in[11];
    const float* film_b    =(const float*)d_in[12];
    const float* edge_w1   =(const float*)d_in[13];
    const float* edge_b1   =(const float*)d_in[14];
    const float* edge_w2   =(const float*)d_in[15];
    const float* edge_b2   =(const float*)d_in[16];
    const float* node_w1   =(const float*)d_in[17];
    const float* node_b1   =(const float*)d_in[18];
    const float* node_w2   =(const float*)d_in[19];
    const float* node_b2   =(const float*)d_in[20];
    const float* w_coord   =(const float*)d_in[21];
    const float* w_latt    =(const float*)d_in[22];
    const float* w_type    =(const float*)d_in[23];
    const float* b_type    =(const float*)d_in[24];
    float* out = (float*)d_out;

    float *nf,*PQ,*no1,*agg,*ef1,*ldb,*w1r,*wPQ,*cond,*lips,*gf,*ltmp;
    { void* p;
      cudaGetSymbolAddress(&p, g_nf);      nf   = (float*)p;
      cudaGetSymbolAddress(&p, g_PQ);      PQ   = (float*)p;
      cudaGetSymbolAddress(&p, g_no1);     no1  = (float*)p;
      cudaGetSymbolAddress(&p, g_agg);     agg  = (float*)p;
      cudaGetSymbolAddress(&p, g_ef1);     ef1  = (float*)p;
      cudaGetSymbolAddress(&p, g_latdemb); ldb  = (float*)p;
      cudaGetSymbolAddress(&p, g_w1r);     w1r  = (float*)p;
      cudaGetSymbolAddress(&p, g_wPQ);     wPQ  = (float*)p;
      cudaGetSymbolAddress(&p, g_cond);    cond = (float*)p;
      cudaGetSymbolAddress(&p, g_latips);  lips = (float*)p;
      cudaGetSymbolAddress(&p, g_gfeat);   gf   = (float*)p;
      cudaGetSymbolAddress(&p, g_lattmp);  ltmp = (float*)p;
    }

    // opt-in to >48KB dynamic smem (idempotent host-side attribute sets)
    cudaFuncSetAttribute(edge1_gemm, cudaFuncAttributeMaxDynamicSharedMemorySize, SMEM_BIG);
    cudaFuncSetAttribute(edge2_gemm, cudaFuncAttributeMaxDynamicSharedMemorySize, SMEM_E2);
    cudaFuncSetAttribute(big_gemm<false,false,false,false>, cudaFuncAttributeMaxDynamicSharedMemorySize, SMEM_BIG);
    cudaFuncSetAttribute(big_gemm<true,true,false,true>,    cudaFuncAttributeMaxDynamicSharedMemorySize, SMEM_BIG);
    cudaFuncSetAttribute(big_gemm<false,true,true,true>,    cudaFuncAttributeMaxDynamicSharedMemorySize, SMEM_BIG);

    // ----- setup -----
    latips_kernel<<<(Bsz*9+255)/256,256>>>(lattices, lips);
    latdemb_kernel<<<(Ee+255)/256,256>>>(frac, lips, ldb);
    gemm_guard_cat(Bsz, 2*Hh, TIMED, TEXTD, t, text, w_cond, TIMED+TEXTD, b_cond, cond, 2*Hh, 1);
    gemm_guard(Nn, Hh, MAXA, atom_types, MAXA, w_emb, MAXA, b_emb, nf, Hh, 0);

    // ----- layers -----
    for (int i=0;i<NLAYERS;i++){
        const float* ew1 = edge_w1 + (size_t)i*Hh*EDGE_IN;
        const float* eb1 = edge_b1 + i*Hh;
        const float* ew2 = edge_w2 + (size_t)i*Hh*Hh;
        const float* eb2 = edge_b2 + i*Hh;
        const float* nw1 = node_w1 + (size_t)i*Hh*2*Hh;
        const float* nb1 = node_b1 + i*Hh;
        const float* nw2 = node_w2 + (size_t)i*Hh*Hh;
        const float* nb2 = node_b2 + i*Hh;

        projfilm<<<Nn/32,256>>>(w_proj, b_proj, cond, film_g, film_b, nf);

        pack_w1r<<<(Hh*LD_PAD+255)/256,256>>>(ew1, w1r);
        pack_wPQ<<<(2*Hh*Hh+255)/256,256>>>(ew1, wPQ);

        // PQ = nf @ wPQ^T  (Nout=512 via 2 col-blocks)
        big_gemm<false,false,false,false><<<dim3(2,Nn/128),256,SMEM_BIG>>>(
            nf, nullptr, 0, wPQ, Hh, nullptr, nullptr, PQ, 2*Hh, Hh);

        // ef1 = silu(latdemb @ w1r^T + P[e0] + Q[e1] + b1)
        edge1_gemm<<<Ee/128,256,SMEM_BIG>>>(ldb, w1r, eb1, PQ, ef1);

        // agg = segment-mean of silu(ef1 @ W2^T + b2)
        edge2_gemm<<<Ee/96,256,SMEM_E2>>>(ef1, ew2, eb2, agg);

        // no1 = silu([nf, agg] @ nw1^T + nb1)
        big_gemm<true,true,false,true><<<dim3(1,Nn/128),256,SMEM_BIG>>>(
            nf, agg, Hh, nw1, 2*Hh, nb1, nullptr, no1, Hh, 2*Hh);

        // nf += silu(no1 @ nw2^T + nb2)
        big_gemm<false,true,true,true><<<dim3(1,Nn/128),256,SMEM_BIG>>>(
            no1, nullptr, 0, nw2, Hh, nb2, nf, nf, Hh, Hh);
    }

    // ----- outputs -----
    gemm_guard(Nn, MAXA, Hh, nf, Hh, w_type, Hh, b_type, out + O_TYPES, MAXA, 0);
    gfeat2<<<(Bsz*Hh+255)/256,256>>>(nf, gf);
    lattmp_kernel<<<(Bsz*9+255)/256,256>>>(gf, w_latt, ltmp);
    lattout_kernel<<<(Bsz*9+255)/256,256>>>(ltmp, lattices, out + O_LATT);
    coords_kernel<<<(Nn*3+255)/256,256>>>(nf, w_coord, out + O_COORD);
    copy_f<<<(Nn*Hh+255)/256,256>>>(nf, out + O_NF, Nn*Hh);
}

// round 8
// speedup vs baseline: 1.0371x; 1.0371x over previous
#include <cuda_runtime.h>
#include <math.h>

// ---------------- problem constants ----------------
#define Hh 256
#define Bsz 128
#define Asz 24
#define Nn (Bsz*Asz)          // 3072 nodes
#define Ee (Bsz*Asz*Asz)      // 73728 edges
#define MAXA 103
#define TIMED 256
#define TEXTD 128
#define NFREQ 10
#define NLAYERS 4
#define EDGE_IN (2*Hh+9+60)   // 581
#define LD_PAD 80             // 9 lat + 60 demb, padded to 80 (5 x BK16)

#define O_TYPES 0
#define O_LATT  (Nn*MAXA)
#define O_COORD (O_LATT + Bsz*9)
#define O_NF    (O_COORD + Nn*3)

typedef unsigned long long ull;

// ---------------- scratch ----------------
__device__ float g_nf[Nn*Hh];
__device__ float g_PQ[Nn*2*Hh];
__device__ float g_no1[Nn*Hh];
__device__ float g_agg[Nn*Hh];
__device__ float g_ef1[(size_t)Ee*Hh];
__device__ float g_latdemb[(size_t)Ee*LD_PAD];
__device__ float g_w1r[Hh*LD_PAD];
__device__ float g_wPQ[2*Hh*Hh];
__device__ float g_cond[Bsz*2*Hh];
__device__ float g_latips[Bsz*9];
__device__ float g_gfeat[Bsz*Hh];
__device__ float g_lattmp[Bsz*9];

__device__ __forceinline__ float siluf(float x){
    float h = 0.5f*x, t;
    asm("tanh.approx.f32 %0, %1;" : "=f"(t) : "f"(h));
    return h*(1.f+t);
}
__device__ __forceinline__ ull pack2(float x, float y){
    ull r; asm("mov.b64 %0, {%1, %2};" : "=l"(r) : "f"(x), "f"(y)); return r;
}
__device__ __forceinline__ void unpack2(ull v, float &x, float &y){
    asm("mov.b64 {%0, %1}, %2;" : "=f"(x), "=f"(y) : "l"(v));
}
__device__ __forceinline__ void fma2(ull &d, ull a, ull b){
    asm("fma.rn.f32x2 %0, %1, %2, %0;" : "+l"(d) : "l"(a), "l"(b));
}

// dynamic smem sizes
#define SMEM_F128 ((2*16*2*128 + 2*16*128)*4)   // 49152 (48KB)
#define SMEM_E2   ((2*16*2*96  + 2*16*128)*4)   // 40960 (40KB)

// =====================================================================
// fast_gemm: BM=128, BN=128, BK=16, TM=8, TN=8, 256 thr, dup-A smem
// grid (Nout/128, M/128)
// =====================================================================
template<bool CONCAT,bool ACT,bool RESID,bool BIAS>
__global__ __launch_bounds__(256,2) void fast_gemm(
    const float* __restrict__ A, const float* __restrict__ A2, int K1,
    const float* __restrict__ W, int ldw,
    const float* __restrict__ bias, const float* __restrict__ resid,
    float* __restrict__ C, int ldc, int K)
{
    const int BM=128,BN=128,BK=16,NT=256;
    extern __shared__ float sm[];
    float* As_ = sm;                 // [2][BK][2*BM] dup pairs
    float* Bs_ = sm + 2*BK*2*BM;     // [2][BK][BN]
    const int tid=threadIdx.x;
    const int tc=tid&15, tr=tid>>4;
    const int m0=blockIdx.y*BM, n0=blockIdx.x*BN;

    ull acc[8][4];
    #pragma unroll
    for(int i=0;i<8;i++)
        #pragma unroll
        for(int j=0;j<4;j++) acc[i][j]=0ULL;

    float4 fa[2], fb[2];
    auto loadA=[&](int k0){
        #pragma unroll
        for(int u=0;u<2;u++){
            int s=tid+u*NT; int mm=s>>2, kq=(s&3)<<2;
            if(CONCAT){
                int gk=k0+kq;
                const float* src=(gk<K1)? A+(size_t)(m0+mm)*K1+gk
                                        : A2+(size_t)(m0+mm)*K1+(gk-K1);
                fa[u]=*(const float4*)src;
            } else fa[u]=*(const float4*)(A+(size_t)(m0+mm)*K+k0+kq);
        }
    };
    auto loadB=[&](int k0){
        #pragma unroll
        for(int u=0;u<2;u++){
            int s=tid+u*NT; int nn=s>>2, kq=(s&3)<<2;
            fb[u]=*(const float4*)(W+(size_t)(n0+nn)*ldw+k0+kq);
        }
    };
    auto storeA=[&](int b){
        #pragma unroll
        for(int u=0;u<2;u++){
            int s=tid+u*NT; int mm=s>>2, kq=(s&3)<<2;
            float v[4]={fa[u].x,fa[u].y,fa[u].z,fa[u].w};
            #pragma unroll
            for(int j=0;j<4;j++)
                *(ull*)&As_[(size_t)(b*BK+kq+j)*(2*BM)+2*mm]=pack2(v[j],v[j]);
        }
    };
    auto storeB=[&](int b){
        #pragma unroll
        for(int u=0;u<2;u++){
            int s=tid+u*NT; int nn=s>>2, kq=(s&3)<<2;
            Bs_[(size_t)(b*BK+kq+0)*BN+nn]=fb[u].x;
            Bs_[(size_t)(b*BK+kq+1)*BN+nn]=fb[u].y;
            Bs_[(size_t)(b*BK+kq+2)*BN+nn]=fb[u].z;
            Bs_[(size_t)(b*BK+kq+3)*BN+nn]=fb[u].w;
        }
    };

    loadA(0); loadB(0); storeA(0); storeB(0); __syncthreads();
    const int ntile=K/BK;
    for(int t=0;t<ntile;t++){
        int cur=t&1;
        if(t+1<ntile){ loadA((t+1)*BK); loadB((t+1)*BK); }
        #pragma unroll
        for(int kk=0;kk<BK;kk++){
            ull av[8], bv[4];
            const float* ar=&As_[(size_t)(cur*BK+kk)*(2*BM)+2*(tr*8)];
            const float* br=&Bs_[(size_t)(cur*BK+kk)*BN+tc*8];
            #pragma unroll
            for(int p=0;p<4;p++){ ulonglong2 t2=*(const ulonglong2*)(ar+4*p); av[2*p]=t2.x; av[2*p+1]=t2.y; }
            #pragma unroll
            for(int q=0;q<2;q++){ ulonglong2 t2=*(const ulonglong2*)(br+4*q); bv[2*q]=t2.x; bv[2*q+1]=t2.y; }
            #pragma unroll
            for(int i=0;i<8;i++)
                #pragma unroll
                for(int j=0;j<4;j++) fma2(acc[i][j],av[i],bv[j]);
        }
        if(t+1<ntile){ int nb=cur^1; storeA(nb); storeB(nb); __syncthreads(); }
    }

    const int col0=n0+tc*8;
    float4 b0,b1;
    if(BIAS){ b0=*(const float4*)(bias+col0); b1=*(const float4*)(bias+col0+4); }
    #pragma unroll
    for(int i=0;i<8;i++){
        int gm=m0+tr*8+i;
        float v[8];
        #pragma unroll
        for(int j=0;j<4;j++) unpack2(acc[i][j], v[2*j], v[2*j+1]);
        if(BIAS){ v[0]+=b0.x; v[1]+=b0.y; v[2]+=b0.z; v[3]+=b0.w;
                  v[4]+=b1.x; v[5]+=b1.y; v[6]+=b1.z; v[7]+=b1.w; }
        if(ACT){
            #pragma unroll
            for(int k=0;k<8;k++) v[k]=siluf(v[k]);
        }
        if(RESID){
            float4 r0=*(const float4*)(resid+(size_t)gm*ldc+col0);
            float4 r1=*(const float4*)(resid+(size_t)gm*ldc+col0+4);
            v[0]+=r0.x; v[1]+=r0.y; v[2]+=r0.z; v[3]+=r0.w;
            v[4]+=r1.x; v[5]+=r1.y; v[6]+=r1.z; v[7]+=r1.w;
        }
        *(float4*)(C+(size_t)gm*ldc+col0)  =make_float4(v[0],v[1],v[2],v[3]);
        *(float4*)(C+(size_t)gm*ldc+col0+4)=make_float4(v[4],v[5],v[6],v[7]);
    }
}

// =====================================================================
// edge1: ef1 = silu(latdemb @ W1r^T + P[e0] + Q[e1] + b1)   K=80
// BM=128, BN=128, BK=16, TM=TN=8. grid (2, Ee/128)
// =====================================================================
__global__ __launch_bounds__(256,2) void edge1_gemm(
    const float* __restrict__ A,    // [Ee][80]
    const float* __restrict__ W,    // [256][80]
    const float* __restrict__ bias,
    const float* __restrict__ PQ,   // [Nn][512]
    float* __restrict__ C)          // [Ee][256]
{
    const int BM=128,BN=128,BK=16,NT=256,K=LD_PAD;
    extern __shared__ float sm[];
    float* As_ = sm;
    float* Bs_ = sm + 2*BK*2*BM;
    const int tid=threadIdx.x;
    const int tc=tid&15, tr=tid>>4;
    const int m0=blockIdx.y*BM, n0=blockIdx.x*BN;

    ull acc[8][4];
    #pragma unroll
    for(int i=0;i<8;i++)
        #pragma unroll
        for(int j=0;j<4;j++) acc[i][j]=0ULL;

    float4 fa[2], fb[2];
    auto loadA=[&](int k0){
        #pragma unroll
        for(int u=0;u<2;u++){
            int s=tid+u*NT; int mm=s>>2, kq=(s&3)<<2;
            fa[u]=*(const float4*)(A+(size_t)(m0+mm)*K+k0+kq);
        }
    };
    auto loadB=[&](int k0){
        #pragma unroll
        for(int u=0;u<2;u++){
            int s=tid+u*NT; int nn=s>>2, kq=(s&3)<<2;
            fb[u]=*(const float4*)(W+(size_t)(n0+nn)*K+k0+kq);
        }
    };
    auto storeA=[&](int b){
        #pragma unroll
        for(int u=0;u<2;u++){
            int s=tid+u*NT; int mm=s>>2, kq=(s&3)<<2;
            float v[4]={fa[u].x,fa[u].y,fa[u].z,fa[u].w};
            #pragma unroll
            for(int j=0;j<4;j++)
                *(ull*)&As_[(size_t)(b*BK+kq+j)*(2*BM)+2*mm]=pack2(v[j],v[j]);
        }
    };
    auto storeB=[&](int b){
        #pragma unroll
        for(int u=0;u<2;u++){
            int s=tid+u*NT; int nn=s>>2, kq=(s&3)<<2;
            Bs_[(size_t)(b*BK+kq+0)*BN+nn]=fb[u].x;
            Bs_[(size_t)(b*BK+kq+1)*BN+nn]=fb[u].y;
            Bs_[(size_t)(b*BK+kq+2)*BN+nn]=fb[u].z;
            Bs_[(size_t)(b*BK+kq+3)*BN+nn]=fb[u].w;
        }
    };

    loadA(0); loadB(0); storeA(0); storeB(0); __syncthreads();
    const int ntile=K/BK; // 5
    for(int t=0;t<ntile;t++){
        int cur=t&1;
        if(t+1<ntile){ loadA((t+1)*BK); loadB((t+1)*BK); }
        #pragma unroll
        for(int kk=0;kk<BK;kk++){
            ull av[8], bv[4];
            const float* ar=&As_[(size_t)(cur*BK+kk)*(2*BM)+2*(tr*8)];
            const float* br=&Bs_[(size_t)(cur*BK+kk)*BN+tc*8];
            #pragma unroll
            for(int p=0;p<4;p++){ ulonglong2 t2=*(const ulonglong2*)(ar+4*p); av[2*p]=t2.x; av[2*p+1]=t2.y; }
            #pragma unroll
            for(int q=0;q<2;q++){ ulonglong2 t2=*(const ulonglong2*)(br+4*q); bv[2*q]=t2.x; bv[2*q+1]=t2.y; }
            #pragma unroll
            for(int i=0;i<8;i++)
                #pragma unroll
                for(int j=0;j<4;j++) fma2(acc[i][j],av[i],bv[j]);
        }
        if(t+1<ntile){ int nb=cur^1; storeA(nb); storeB(nb); __syncthreads(); }
    }

    const int col0=n0+tc*8;
    float4 b0=*(const float4*)(bias+col0);
    float4 b1=*(const float4*)(bias+col0+4);
    #pragma unroll
    for(int i=0;i<8;i++){
        int gm=m0+tr*8+i;
        int b=gm/(Asz*Asz), w=gm%(Asz*Asz);
        int e0=b*Asz+w/Asz, e1=b*Asz+w%Asz;
        const float* pp=PQ+(size_t)e0*(2*Hh)+col0;
        const float* qq=PQ+(size_t)e1*(2*Hh)+Hh+col0;
        float4 p0=*(const float4*)pp,     p1=*(const float4*)(pp+4);
        float4 q0=*(const float4*)qq,     q1=*(const float4*)(qq+4);
        float v[8];
        #pragma unroll
        for(int j=0;j<4;j++) unpack2(acc[i][j], v[2*j], v[2*j+1]);
        v[0]=siluf(v[0]+b0.x+p0.x+q0.x); v[1]=siluf(v[1]+b0.y+p0.y+q0.y);
        v[2]=siluf(v[2]+b0.z+p0.z+q0.z); v[3]=siluf(v[3]+b0.w+p0.w+q0.w);
        v[4]=siluf(v[4]+b1.x+p1.x+q1.x); v[5]=siluf(v[5]+b1.y+p1.y+q1.y);
        v[6]=siluf(v[6]+b1.z+p1.z+q1.z); v[7]=siluf(v[7]+b1.w+p1.w+q1.w);
        *(float4*)(C+(size_t)gm*Hh+col0)  =make_float4(v[0],v[1],v[2],v[3]);
        *(float4*)(C+(size_t)gm*Hh+col0+4)=make_float4(v[4],v[5],v[6],v[7]);
    }
}

// =====================================================================
// edge2: agg[n] = mean_{24 edges} silu(ef1 @ W2^T + b2)
// BM=96 (=4 nodes), TM=6, BN=128, BK=16. In-block reduction, no atomics.
// grid (2, Ee/96)
// =====================================================================
__global__ __launch_bounds__(256,2) void edge2_gemm(
    const float* __restrict__ A,    // ef1 [Ee][256]
    const float* __restrict__ W,    // [256][256]
    const float* __restrict__ bias,
    float* __restrict__ agg)        // [Nn][256]
{
    const int BM=96,BN=128,BK=16,NT=256,K=Hh;
    extern __shared__ float sm[];
    float* As_ = sm;                 // [2][BK][2*BM] = 6144 f
    float* Bs_ = sm + 2*BK*2*BM;     // [2][BK][BN]   = 4096 f
    float* red = Bs_;                // alias after mainloop (needs 2048 f)
    const int tid=threadIdx.x;
    const int tc=tid&15, tr=tid>>4;
    const int m0=blockIdx.y*BM, n0=blockIdx.x*BN;

    ull acc[6][4];
    #pragma unroll
    for(int i=0;i<6;i++)
        #pragma unroll
        for(int j=0;j<4;j++) acc[i][j]=0ULL;

    float4 fa[2], fb[2];
    auto loadA=[&](int k0){
        #pragma unroll
        for(int u=0;u<2;u++){
            int s=tid+u*NT;
            if(s<384){ int mm=s>>2, kq=(s&3)<<2;
                fa[u]=*(const float4*)(A+(size_t)(m0+mm)*K+k0+kq); }
        }
    };
    auto loadB=[&](int k0){
        #pragma unroll
        for(int u=0;u<2;u++){
            int s=tid+u*NT; int nn=s>>2, kq=(s&3)<<2;
            fb[u]=*(const float4*)(W+(size_t)(n0+nn)*K+k0+kq);
        }
    };
    auto storeA=[&](int b){
        #pragma unroll
        for(int u=0;u<2;u++){
            int s=tid+u*NT;
            if(s<384){ int mm=s>>2, kq=(s&3)<<2;
                float v[4]={fa[u].x,fa[u].y,fa[u].z,fa[u].w};
                #pragma unroll
                for(int j=0;j<4;j++)
                    *(ull*)&As_[(size_t)(b*BK+kq+j)*(2*BM)+2*mm]=pack2(v[j],v[j]);
            }
        }
    };
    auto storeB=[&](int b){
        #pragma unroll
        for(int u=0;u<2;u++){
            int s=tid+u*NT; int nn=s>>2, kq=(s&3)<<2;
            Bs_[(size_t)(b*BK+kq+0)*BN+nn]=fb[u].x;
            Bs_[(size_t)(b*BK+kq+1)*BN+nn]=fb[u].y;
            Bs_[(size_t)(b*BK+kq+2)*BN+nn]=fb[u].z;
            Bs_[(size_t)(b*BK+kq+3)*BN+nn]=fb[u].w;
        }
    };

    loadA(0); loadB(0); storeA(0); storeB(0); __syncthreads();
    const int ntile=K/BK; // 16
    for(int t=0;t<ntile;t++){
        int cur=t&1;
        if(t+1<ntile){ loadA((t+1)*BK); loadB((t+1)*BK); }
        #pragma unroll
        for(int kk=0;kk<BK;kk++){
            ull av[6], bv[4];
            const float* ar=&As_[(size_t)(cur*BK+kk)*(2*BM)+2*(tr*6)];
            const float* br=&Bs_[(size_t)(cur*BK+kk)*BN+tc*8];
            #pragma unroll
            for(int p=0;p<3;p++){ ulonglong2 t2=*(const ulonglong2*)(ar+4*p); av[2*p]=t2.x; av[2*p+1]=t2.y; }
            #pragma unroll
            for(int q=0;q<2;q++){ ulonglong2 t2=*(const ulonglong2*)(br+4*q); bv[2*q]=t2.x; bv[2*q+1]=t2.y; }
            #pragma unroll
            for(int i=0;i<6;i++)
                #pragma unroll
                for(int j=0;j<4;j++) fma2(acc[i][j],av[i],bv[j]);
        }
        if(t+1<ntile){ int nb=cur^1; storeA(nb); storeB(nb); __syncthreads(); }
    }

    // silu + per-thread partial sums (each thread's 6 rows are within one node)
    const int col0=tc*8;
    float4 b0=*(const float4*)(bias+n0+col0);
    float4 b1=*(const float4*)(bias+n0+col0+4);
    float cs[8]={0,0,0,0,0,0,0,0};
    #pragma unroll
    for(int i=0;i<6;i++){
        float v[8];
        #pragma unroll
        for(int j=0;j<4;j++) unpack2(acc[i][j], v[2*j], v[2*j+1]);
        cs[0]+=siluf(v[0]+b0.x); cs[1]+=siluf(v[1]+b0.y);
        cs[2]+=siluf(v[2]+b0.z); cs[3]+=siluf(v[3]+b0.w);
        cs[4]+=siluf(v[4]+b1.x); cs[5]+=siluf(v[5]+b1.y);
        cs[6]+=siluf(v[6]+b1.z); cs[7]+=siluf(v[7]+b1.w);
    }
    __syncthreads();   // done with Bs; reuse as red[16][128]
    *(float4*)&red[(size_t)tr*BN+col0]  =make_float4(cs[0],cs[1],cs[2],cs[3]);
    *(float4*)&red[(size_t)tr*BN+col0+4]=make_float4(cs[4],cs[5],cs[6],cs[7]);
    __syncthreads();
    if((tr&3)==0){
        int node = blockIdx.y*4 + (tr>>2);
        #pragma unroll
        for(int q=0;q<2;q++){
            float4 r0=*(const float4*)&red[(size_t)(tr+0)*BN+col0+4*q];
            float4 r1=*(const float4*)&red[(size_t)(tr+1)*BN+col0+4*q];
            float4 r2=*(const float4*)&red[(size_t)(tr+2)*BN+col0+4*q];
            float4 r3=*(const float4*)&red[(size_t)(tr+3)*BN+col0+4*q];
            float4 o=make_float4((r0.x+r1.x+r2.x+r3.x)*(1.f/24.f),
                                 (r0.y+r1.y+r2.y+r3.y)*(1.f/24.f),
                                 (r0.z+r1.z+r2.z+r3.z)*(1.f/24.f),
                                 (r0.w+r1.w+r2.w+r3.w)*(1.f/24.f));
            *(float4*)(agg+(size_t)node*Hh+n0+col0+4*q)=o;
        }
    }
}

// ===== fused: y = nf@w_proj^T + b; nf += silu((LN(y)*fg+fb)*scale + shift) =====
__global__ __launch_bounds__(256) void projfilm(
    const float* __restrict__ wproj, const float* __restrict__ bproj,
    const float* __restrict__ cond,
    const float* __restrict__ fg, const float* __restrict__ fb,
    float* nf)
{
    const int BM=32,BN=256,BK=8,TM=4,TN=8,NT=256,K=Hh;
    __shared__ __align__(16) float As[2][BK][BM];
    __shared__ __align__(16) float Bs[2][BK][BN];
    const int tid=threadIdx.x;
    const int tc=tid%32, tr=tid/32;
    const int m0=blockIdx.x*BM;

    ull acc[TM][TN/2];
    #pragma unroll
    for(int i=0;i<TM;i++)
        #pragma unroll
        for(int j=0;j<TN/2;j++) acc[i][j]=0ULL;

    float ra[1], rb[8];
    { int i=tid; ra[0]=nf[(size_t)(m0+i/BK)*K + i%BK]; }
    #pragma unroll
    for(int u=0;u<8;u++){int i=tid+u*NT; rb[u]=wproj[(size_t)(i/BK)*K + i%BK];}
    { int i=tid; As[0][i%BK][i/BK]=ra[0]; }
    #pragma unroll
    for(int u=0;u<8;u++){int i=tid+u*NT; Bs[0][i%BK][i/BK]=rb[u];}
    __syncthreads();

    const int ntile=K/BK;
    for(int t=0;t<ntile;t++){
        int cur=t&1;
        if(t+1<ntile){
            int k0=(t+1)*BK;
            { int i=tid; ra[0]=nf[(size_t)(m0+i/BK)*K + k0 + i%BK]; }
            #pragma unroll
            for(int u=0;u<8;u++){int i=tid+u*NT; rb[u]=wproj[(size_t)(i/BK)*K + k0 + i%BK];}
        }
        #pragma unroll
        for(int kk=0;kk<BK;kk++){
            ull av[TM], bv[TN/2];
            #pragma unroll
            for(int i=0;i<TM;i++){ float a=As[cur][kk][tr*TM+i]; av[i]=pack2(a,a); }
            #pragma unroll
            for(int j=0;j<TN/2;j++) bv[j]=*reinterpret_cast<const ull*>(&Bs[cur][kk][tc*TN+2*j]);
            #pragma unroll
            for(int i=0;i<TM;i++)
                #pragma unroll
                for(int j=0;j<TN/2;j++) fma2(acc[i][j],av[i],bv[j]);
        }
        if(t+1<ntile){
            int nb=cur^1;
            { int i=tid; As[nb][i%BK][i/BK]=ra[0]; }
            #pragma unroll
            for(int u=0;u<8;u++){int i=tid+u*NT; Bs[nb][i%BK][i/BK]=rb[u];}
            __syncthreads();
        }
    }

    const int col0 = tc*TN;
    #pragma unroll
    for(int i=0;i<TM;i++){
        int gm = m0 + tr*TM + i;
        int g  = gm/Asz;
        float v[8];
        #pragma unroll
        for(int j=0;j<TN/2;j++) unpack2(acc[i][j], v[2*j], v[2*j+1]);
        #pragma unroll
        for(int jj=0;jj<8;jj++) v[jj] += bproj[col0+jj];
        float s=0.f;
        #pragma unroll
        for(int jj=0;jj<8;jj++) s+=v[jj];
        #pragma unroll
        for(int o=16;o>0;o>>=1) s += __shfl_xor_sync(0xffffffffu, s, o);
        float mu = s*(1.0f/256.0f);
        float ss=0.f;
        #pragma unroll
        for(int jj=0;jj<8;jj++){ v[jj]-=mu; ss+=v[jj]*v[jj]; }
        #pragma unroll
        for(int o=16;o>0;o>>=1) ss += __shfl_xor_sync(0xffffffffu, ss, o);
        float rstd = rsqrtf(ss*(1.0f/256.0f) + 1e-5f);
        #pragma unroll
        for(int jj=0;jj<8;jj++){
            int col = col0+jj;
            float y  = v[jj]*rstd*fg[col] + fb[col];
            float sc = cond[(size_t)g*(2*Hh)+col];
            float sh = cond[(size_t)g*(2*Hh)+Hh+col];
            nf[(size_t)gm*Hh+col] += siluf(y*sc + sh);
        }
    }
}

// ================= guarded GEMM (cold paths) ========
template<int BM,int BN,int BK,int TM,int TN,int AMODE>
__global__ void gemm_k(
    int M, int Nout, int K,
    const float* __restrict__ A, int lda,
    const float* __restrict__ A2, int K1, int lda2,
    const float* __restrict__ W, int ldw,
    const float* __restrict__ bias,
    float* __restrict__ C, int ldc,
    int act)
{
    __shared__ float As[BK][BM];
    __shared__ float Bs[BK][BN];
    const int NT = (BM/TM)*(BN/TN);
    const int tid = threadIdx.x;
    const int tc  = tid % (BN/TN);
    const int tr  = tid / (BN/TN);
    const int m0  = blockIdx.y * BM;
    const int n0  = blockIdx.x * BN;

    float acc[TM][TN];
    #pragma unroll
    for (int i=0;i<TM;i++)
        #pragma unroll
        for (int j=0;j<TN;j++) acc[i][j]=0.f;

    for (int k0 = 0; k0 < K; k0 += BK) {
        for (int i = tid; i < BM*BK; i += NT) {
            int mm = i / BK, kk = i % BK;
            int gm = m0 + mm, gk = k0 + kk;
            float v = 0.f;
            if (gm < M && gk < K) {
                if (AMODE == 0) v = A[(size_t)gm*lda + gk];
                else v = (gk < K1) ? A[(size_t)gm*lda + gk] : A2[(size_t)gm*lda2 + (gk-K1)];
            }
            As[kk][mm] = v;
        }
        for (int i = tid; i < BN*BK; i += NT) {
            int nn = i / BK, kk = i % BK;
            int gn = n0 + nn, gk = k0 + kk;
            Bs[kk][nn] = (gn < Nout && gk < K) ? W[(size_t)gn*ldw + gk] : 0.f;
        }
        __syncthreads();
        #pragma unroll
        for (int kk = 0; kk < BK; kk++) {
            float a[TM], b[TN];
            #pragma unroll
            for (int i=0;i<TM;i++) a[i] = As[kk][tr*TM+i];
            #pragma unroll
            for (int j=0;j<TN;j++) b[j] = Bs[kk][tc*TN+j];
            #pragma unroll
            for (int i=0;i<TM;i++)
                #pragma unroll
                for (int j=0;j<TN;j++) acc[i][j] += a[i]*b[j];
        }
        __syncthreads();
    }

    #pragma unroll
    for (int i=0;i<TM;i++) {
        int gm = m0 + tr*TM + i;
        if (gm >= M) continue;
        #pragma unroll
        for (int j=0;j<TN;j++) {
            int gn = n0 + tc*TN + j;
            if (gn >= Nout) continue;
            float v = acc[i][j];
            if (bias) v += bias[gn];
            if (act)  v = siluf(v);
            C[(size_t)gm*ldc + gn] = v;
        }
    }
}

// ---------------- small kernels ----------------
__global__ void copy_f(const float* __restrict__ a, float* __restrict__ b, int n){
    int i=blockIdx.x*blockDim.x+threadIdx.x; if(i<n) b[i]=a[i];
}
__global__ void latips_kernel(const float* __restrict__ L, float* __restrict__ out){
    int idx = blockIdx.x*blockDim.x+threadIdx.x;
    if (idx >= Bsz*9) return;
    int b = idx/9, r = idx%9, i = r/3, k = r%3;
    out[idx] = L[b*9+i*3+0]*L[b*9+k*3+0] + L[b*9+i*3+1]*L[b*9+k*3+1] + L[b*9+i*3+2]*L[b*9+k*3+2];
}
__global__ void latdemb_kernel(const float* __restrict__ fc, const float* __restrict__ latips,
                               float* __restrict__ out){
    int e = blockIdx.x*blockDim.x+threadIdx.x;
    if (e >= Ee) return;
    int b = e/(Asz*Asz), w = e%(Asz*Asz);
    int a = b*Asz + w/Asz, c = b*Asz + w%Asz;
    float* o = out + (size_t)e*LD_PAD;
    #pragma unroll
    for (int i=0;i<9;i++) o[i] = latips[b*9+i];
    #pragma unroll
    for (int d=0;d<3;d++){
        float df = fc[c*3+d] - fc[a*3+d];
        df -= floorf(df);
        #pragma unroll
        for (int f=0;f<NFREQ;f++){
            float ang = 6.283185307179586f * (float)f * df;
            float sn, cs; sincosf(ang, &sn, &cs);
            o[9 + d*NFREQ + f]      = sn;
            o[9 + 30 + d*NFREQ + f] = cs;
        }
    }
    #pragma unroll
    for (int i=69;i<LD_PAD;i++) o[i]=0.f;
}
__global__ void pack_w1r(const float* __restrict__ ew1, float* __restrict__ w1r){
    int i = blockIdx.x*blockDim.x+threadIdx.x;
    if (i >= Hh*LD_PAD) return;
    int n = i/LD_PAD, k = i%LD_PAD;
    w1r[i] = (k < 69) ? ew1[(size_t)n*EDGE_IN + 2*Hh + k] : 0.f;
}
__global__ void pack_wPQ(const float* __restrict__ ew1, float* __restrict__ wPQ){
    int i = blockIdx.x*blockDim.x+threadIdx.x;
    if (i >= 2*Hh*Hh) return;
    int n = i/Hh, k = i%Hh;
    wPQ[i] = (n < Hh) ? ew1[(size_t)n*EDGE_IN + k] : ew1[(size_t)(n-Hh)*EDGE_IN + Hh + k];
}
__global__ void gfeat2(const float* __restrict__ nf, float* __restrict__ gf){
    int i=blockIdx.x*blockDim.x+threadIdx.x;
    if (i >= Bsz*Hh) return;
    int b=i/Hh, h=i%Hh;
    float s=0.f;
    #pragma unroll
    for(int a=0;a<Asz;a++) s += nf[(size_t)(b*Asz+a)*Hh+h];
    gf[i]=s;
}
__global__ void lattmp_kernel(const float* __restrict__ gf, const float* __restrict__ w_latt,
                              float* __restrict__ lt){
    int idx = blockIdx.x*blockDim.x+threadIdx.x;
    if (idx >= Bsz*9) return;
    int b = idx/9, r = idx%9;
    float s = 0.f;
    for (int k=0;k<Hh;k++) s += gf[b*Hh+k]*w_latt[r*Hh+k];
    lt[idx] = s * (1.f/(float)Asz);
}
__global__ void lattout_kernel(const float* __restrict__ lt, const float* __restrict__ L,
                               float* __restrict__ out){
    int idx = blockIdx.x*blockDim.x+threadIdx.x;
    if (idx >= Bsz*9) return;
    int b = idx/9, r = idx%9, i = r/3, k = r%3;
    float s = 0.f;
    #pragma unroll
    for (int j=0;j<3;j++) s += lt[b*9+i*3+j]*L[b*9+j*3+k];
    out[idx] = s;
}
__global__ void coords_kernel(const float* __restrict__ nf, const float* __restrict__ wc,
                              float* __restrict__ out){
    int idx = blockIdx.x*blockDim.x+threadIdx.x;
    if (idx >= Nn*3) return;
    int n = idx/3, d = idx%3;
    float s = 0.f;
    for (int k=0;k<Hh;k++) s += nf[(size_t)n*Hh+k]*wc[d*Hh+k];
    out[idx] = s;
}

// ---------------- host helpers ----------------
static void gemm_guard(int M,int Nout,int K, const float* A,int lda,
                       const float* W,int ldw, const float* bias,
                       float* C,int ldc,int act){
    dim3 grid((Nout+63)/64, (M+63)/64);
    gemm_k<64,64,16,4,4,0><<<grid,256>>>(M,Nout,K, A,lda, nullptr,0,0,
        W,ldw,bias, C,ldc, act);
}
static void gemm_guard_cat(int M,int Nout,int K1,int K2, const float* A1,const float* A2,
                           const float* W,int ldw,const float* bias,
                           float* C,int ldc,int act){
    dim3 grid((Nout+63)/64, (M+63)/64);
    gemm_k<64,64,16,4,4,1><<<grid,256>>>(M,Nout,K1+K2, A1,K1, A2,K1,K2,
        W,ldw,bias, C,ldc, act);
}

extern "C" void kernel_launch(void* const* d_in, const int* in_sizes, int n_in,
                              void* d_out, int out_size){
    const float* atom_types=(const float*)d_in[0];
    const float* frac      =(const float*)d_in[1];
    const float* lattices  =(const float*)d_in[2];
    const float* t         =(const float*)d_in[3];
    const float* text      =(const float*)d_in[4];
    const float* w_emb     =(const float*)d_in[5];
    const float* b_emb     =(const float*)d_in[6];
    const float* w_cond    =(const float*)d_in[7];
    const float* b_cond    =(const float*)d_in[8];
    const float* w_proj    =(const float*)d_in[9];
    const float* b_proj    =(const float*)d_in[10];
    const float* film_g    =(const float*)d_in[11];
    const float* film_b    =(const float*)d_in[12];
    const float* edge_w1   =(const float*)d_in[13];
    const float* edge_b1   =(const float*)d_in[14];
    const float* edge_w2   =(const float*)d_in[15];
    const float* edge_b2   =(const float*)d_in[16];
    const float* node_w1   =(const float*)d_in[17];
    const float* node_b1   =(const float*)d_in[18];
    const float* node_w2   =(const float*)d_in[19];
    const float* node_b2   =(const float*)d_in[20];
    const float* w_coord   =(const float*)d_in[21];
    const float* w_latt    =(const float*)d_in[22];
    const float* w_type    =(const float*)d_in[23];
    const float* b_type    =(const float*)d_in[24];
    float* out = (float*)d_out;

    float *nf,*PQ,*no1,*agg,*ef1,*ldb,*w1r,*wPQ,*cond,*lips,*gf,*ltmp;
    { void* p;
      cudaGetSymbolAddress(&p, g_nf);      nf   = (float*)p;
      cudaGetSymbolAddress(&p, g_PQ);      PQ   = (float*)p;
      cudaGetSymbolAddress(&p, g_no1);     no1  = (float*)p;
      cudaGetSymbolAddress(&p, g_agg);     agg  = (float*)p;
      cudaGetSymbolAddress(&p, g_ef1);     ef1  = (float*)p;
      cudaGetSymbolAddress(&p, g_latdemb); ldb  = (float*)p;
      cudaGetSymbolAddress(&p, g_w1r);     w1r  = (float*)p;
      cudaGetSymbolAddress(&p, g_wPQ);     wPQ  = (float*)p;
      cudaGetSymbolAddress(&p, g_cond);    cond = (float*)p;
      cudaGetSymbolAddress(&p, g_latips);  lips = (float*)p;
      cudaGetSymbolAddress(&p, g_gfeat);   gf   = (float*)p;
      cudaGetSymbolAddress(&p, g_lattmp);  ltmp = (float*)p;
    }

    cudaFuncSetAttribute(edge1_gemm, cudaFuncAttributeMaxDynamicSharedMemorySize, SMEM_F128);
    cudaFuncSetAttribute(edge2_gemm, cudaFuncAttributeMaxDynamicSharedMemorySize, SMEM_E2);
    cudaFuncSetAttribute(fast_gemm<false,false,false,false>, cudaFuncAttributeMaxDynamicSharedMemorySize, SMEM_F128);
    cudaFuncSetAttribute(fast_gemm<true,true,false,true>,    cudaFuncAttributeMaxDynamicSharedMemorySize, SMEM_F128);
    cudaFuncSetAttribute(fast_gemm<false,true,true,true>,    cudaFuncAttributeMaxDynamicSharedMemorySize, SMEM_F128);

    // ----- setup -----
    latips_kernel<<<(Bsz*9+255)/256,256>>>(lattices, lips);
    latdemb_kernel<<<(Ee+255)/256,256>>>(frac, lips, ldb);
    gemm_guard_cat(Bsz, 2*Hh, TIMED, TEXTD, t, text, w_cond, TIMED+TEXTD, b_cond, cond, 2*Hh, 1);
    gemm_guard(Nn, Hh, MAXA, atom_types, MAXA, w_emb, MAXA, b_emb, nf, Hh, 0);

    // ----- layers -----
    for (int i=0;i<NLAYERS;i++){
        const float* ew1 = edge_w1 + (size_t)i*Hh*EDGE_IN;
        const float* eb1 = edge_b1 + i*Hh;
        const float* ew2 = edge_w2 + (size_t)i*Hh*Hh;
        const float* eb2 = edge_b2 + i*Hh;
        const float* nw1 = node_w1 + (size_t)i*Hh*2*Hh;
        const float* nb1 = node_b1 + i*Hh;
        const float* nw2 = node_w2 + (size_t)i*Hh*Hh;
        const float* nb2 = node_b2 + i*Hh;

        projfilm<<<Nn/32,256>>>(w_proj, b_proj, cond, film_g, film_b, nf);

        pack_w1r<<<(Hh*LD_PAD+255)/256,256>>>(ew1, w1r);
        pack_wPQ<<<(2*Hh*Hh+255)/256,256>>>(ew1, wPQ);

        // PQ = nf @ wPQ^T  (Nout=512)
        fast_gemm<false,false,false,false><<<dim3(4,Nn/128),256,SMEM_F128>>>(
            nf, nullptr, 0, wPQ, Hh, nullptr, nullptr, PQ, 2*Hh, Hh);

        // ef1 = silu(latdemb @ w1r^T + P[e0] + Q[e1] + b1)
        edge1_gemm<<<dim3(2,Ee/128),256,SMEM_F128>>>(ldb, w1r, eb1, PQ, ef1);

        // agg = segment-mean of silu(ef1 @ W2^T + b2)
        edge2_gemm<<<dim3(2,Ee/96),256,SMEM_E2>>>(ef1, ew2, eb2, agg);

        // no1 = silu([nf, agg] @ nw1^T + nb1)
        fast_gemm<true,true,false,true><<<dim3(2,Nn/128),256,SMEM_F128>>>(
            nf, agg, Hh, nw1, 2*Hh, nb1, nullptr, no1, Hh, 2*Hh);

        // nf += silu(no1 @ nw2^T + nb2)
        fast_gemm<false,true,true,true><<<dim3(2,Nn/128),256,SMEM_F128>>>(
            no1, nullptr, 0, nw2, Hh, nb2, nf, nf, Hh, Hh);
    }

    // ----- outputs -----
    gemm_guard(Nn, MAXA, Hh, nf, Hh, w_type, Hh, b_type, out + O_TYPES, MAXA, 0);
    gfeat2<<<(Bsz*Hh+255)/256,256>>>(nf, gf);
    lattmp_kernel<<<(Bsz*9+255)/256,256>>>(gf, w_latt, ltmp);
    lattout_kernel<<<(Bsz*9+255)/256,256>>>(ltmp, lattices, out + O_LATT);
    coords_kernel<<<(Nn*3+255)/256,256>>>(nf, w_coord, out + O_COORD);
    copy_f<<<(Nn*Hh+255)/256,256>>>(nf, out + O_NF, Nn*Hh);
}

// round 9
// speedup vs baseline: 1.0758x; 1.0373x over previous
#include <cuda_runtime.h>
#include <math.h>

// ---------------- problem constants ----------------
#define Hh 256
#define Bsz 128
#define Asz 24
#define Nn (Bsz*Asz)          // 3072 nodes
#define Ee (Bsz*Asz*Asz)      // 73728 edges
#define MAXA 103
#define TIMED 256
#define TEXTD 128
#define NFREQ 10
#define NLAYERS 4
#define DISD (NFREQ*2*3)      // 60
#define EDGE_IN (2*Hh+9+DISD) // 581
#define LD_PAD 72             // 9 lat + 60 demb, padded to 72 (9 x BK8)

// output layout: atom_types_out | lattice_out | coords_out | nf
#define O_TYPES 0
#define O_LATT  (Nn*MAXA)
#define O_COORD (O_LATT + Bsz*9)
#define O_NF    (O_COORD + Nn*3)

typedef unsigned long long ull;

// ---------------- scratch ----------------
__device__ float g_nf[Nn*Hh];
__device__ float g_PQ[Nn*2*Hh];
__device__ float g_no1[Nn*Hh];
__device__ float g_agg[Nn*Hh];
__device__ float g_ef1[(size_t)Ee*Hh];
__device__ float g_latdemb[(size_t)Ee*LD_PAD];
__device__ float g_w1r[Hh*LD_PAD];
__device__ float g_cond[Bsz*2*Hh];
__device__ float g_latips[Bsz*9];
__device__ float g_gfeat[Bsz*Hh];
__device__ float g_lattmp[Bsz*9];

__device__ __forceinline__ float siluf(float x){
    float h = 0.5f*x, t;
    asm("tanh.approx.f32 %0, %1;" : "=f"(t) : "f"(h));
    return h*(1.f+t);
}
__device__ __forceinline__ ull pack2(float x, float y){
    ull r; asm("mov.b64 %0, {%1, %2};" : "=l"(r) : "f"(x), "f"(y)); return r;
}
__device__ __forceinline__ void unpack2(ull v, float &x, float &y){
    asm("mov.b64 {%0, %1}, %2;" : "=f"(x), "=f"(y) : "l"(v));
}
__device__ __forceinline__ void fma2(ull &d, ull a, ull b){
    asm("fma.rn.f32x2 %0, %1, %2, %0;" : "+l"(d) : "l"(a), "l"(b));
}

// ================= fast node GEMM: 64x64x8, TM=TN=4, f32x2 =================
// (unchanged from the proven 2986us version)
template<bool CONCAT,bool WSPLIT,bool ACT,bool RESID>
__global__ __launch_bounds__(256) void node_gemm(
    const float* __restrict__ A,
    const float* __restrict__ A2, float s2,
    const float* __restrict__ W, int ldw,
    const float* __restrict__ bias,
    const float* resid,
    float* C, int Nout, int K)
{
    const int BM=64,BN=64,BK=8,TM=4,TN=4,NT=256;
    __shared__ __align__(16) float As[2][BK][BM];
    __shared__ __align__(16) float Bs[2][BK][BN];
    const int tid=threadIdx.x;
    const int tc=tid%(BN/TN), tr=tid/(BN/TN);
    const int m0=blockIdx.y*BM, n0=blockIdx.x*BN;

    ull acc[TM][TN/2];
    #pragma unroll
    for(int i=0;i<TM;i++)
        #pragma unroll
        for(int j=0;j<TN/2;j++) acc[i][j]=0ULL;

    float ra[2], rb[2];
    #pragma unroll
    for(int u=0;u<2;u++){
        int i=tid+u*NT; int mm=i/BK, kk=i%BK;
        int gm=m0+mm, gk=kk;
        if(CONCAT) ra[u] = (gk<Hh)? A[(size_t)gm*Hh+gk] : A2[(size_t)gm*Hh+gk-Hh]*s2;
        else       ra[u] = A[(size_t)gm*K+gk];
    }
    #pragma unroll
    for(int u=0;u<2;u++){
        int i=tid+u*NT; int nn=i/BK, kk=i%BK;
        int gn=n0+nn, gk=kk;
        if(WSPLIT) rb[u] = (gn<Hh)? W[(size_t)gn*ldw+gk] : W[(size_t)(gn-Hh)*ldw+Hh+gk];
        else       rb[u] = W[(size_t)gn*ldw+gk];
    }
    #pragma unroll
    for(int u=0;u<2;u++){int i=tid+u*NT; As[0][i%BK][i/BK]=ra[u];}
    #pragma unroll
    for(int u=0;u<2;u++){int i=tid+u*NT; Bs[0][i%BK][i/BK]=rb[u];}
    __syncthreads();

    const int ntile=K/BK;
    for(int t=0;t<ntile;t++){
        int cur=t&1;
        if(t+1<ntile){
            int k0=(t+1)*BK;
            #pragma unroll
            for(int u=0;u<2;u++){
                int i=tid+u*NT; int mm=i/BK, kk=i%BK;
                int gm=m0+mm, gk=k0+kk;
                if(CONCAT) ra[u] = (gk<Hh)? A[(size_t)gm*Hh+gk] : A2[(size_t)gm*Hh+gk-Hh]*s2;
                else       ra[u] = A[(size_t)gm*K+gk];
            }
            #pragma unroll
            for(int u=0;u<2;u++){
                int i=tid+u*NT; int nn=i/BK, kk=i%BK;
                int gn=n0+nn, gk=k0+kk;
                if(WSPLIT) rb[u] = (gn<Hh)? W[(size_t)gn*ldw+gk] : W[(size_t)(gn-Hh)*ldw+Hh+gk];
                else       rb[u] = W[(size_t)gn*ldw+gk];
            }
        }
        #pragma unroll
        for(int kk=0;kk<BK;kk++){
            ull av[TM], bv[TN/2];
            #pragma unroll
            for(int i=0;i<TM;i++){ float a=As[cur][kk][tr*TM+i]; av[i]=pack2(a,a); }
            #pragma unroll
            for(int j=0;j<TN/2;j++) bv[j]=*reinterpret_cast<const ull*>(&Bs[cur][kk][tc*TN+2*j]);
            #pragma unroll
            for(int i=0;i<TM;i++)
                #pragma unroll
                for(int j=0;j<TN/2;j++) fma2(acc[i][j],av[i],bv[j]);
        }
        if(t+1<ntile){
            int nb=cur^1;
            #pragma unroll
            for(int u=0;u<2;u++){int i=tid+u*NT; As[nb][i%BK][i/BK]=ra[u];}
            #pragma unroll
            for(int u=0;u<2;u++){int i=tid+u*NT; Bs[nb][i%BK][i/BK]=rb[u];}
            __syncthreads();
        }
    }

    #pragma unroll
    for(int i=0;i<TM;i++){
        int gm=m0+tr*TM+i;
        #pragma unroll
        for(int j=0;j<TN/2;j++){
            float v0,v1; unpack2(acc[i][j],v0,v1);
            int col=n0+tc*TN+2*j;
            if(bias){ v0+=bias[col]; v1+=bias[col+1]; }
            if(ACT){ v0=siluf(v0); v1=siluf(v1); }
            if(RESID){ v0+=resid[(size_t)gm*Nout+col]; v1+=resid[(size_t)gm*Nout+col+1]; }
            C[(size_t)gm*Nout+col]=v0; C[(size_t)gm*Nout+col+1]=v1;
        }
    }
}

// ================= edge GEMM1: ef1 = silu(latdemb@W1r^T + P[e0]+Q[e1]+b1) ====
// 128x128x8, TM=TN=8, K=72. Dup-A static smem (24KB): inner = 6x LDS.128 + 32 fma2.
__global__ __launch_bounds__(256) void edge1_gemm(
    const float* __restrict__ A,    // [Ee][72]
    const float* __restrict__ W,    // [256][72] packed
    const float* __restrict__ bias, // [256]
    const float* __restrict__ PQ,   // [Nn][512]
    float* __restrict__ C)          // [Ee][256]
{
    const int BM=128,BN=128,BK=8,K=LD_PAD;
    __shared__ __align__(16) float As[2][BK][2*BM];  // duplicated pairs
    __shared__ __align__(16) float Bs[2][BK][BN];
    const int tid=threadIdx.x;
    const int tc=tid&15, tr=tid>>4;
    const int m0=blockIdx.y*BM, n0=blockIdx.x*BN;
    const int mm=tid>>1, kq=(tid&1)<<2;   // staging role: one float4 each for A and B

    ull acc[8][4];
    #pragma unroll
    for(int i=0;i<8;i++)
        #pragma unroll
        for(int j=0;j<4;j++) acc[i][j]=0ULL;

    float4 fa, fb;
    fa=*(const float4*)(A+(size_t)(m0+mm)*K+kq);
    fb=*(const float4*)(W+(size_t)(n0+mm)*K+kq);
    {   float v[4]={fa.x,fa.y,fa.z,fa.w};
        #pragma unroll
        for(int j=0;j<4;j++) *(ull*)&As[0][kq+j][2*mm]=pack2(v[j],v[j]);
        Bs[0][kq+0][mm]=fb.x; Bs[0][kq+1][mm]=fb.y; Bs[0][kq+2][mm]=fb.z; Bs[0][kq+3][mm]=fb.w;
    }
    __syncthreads();

    const int ntile=K/BK; // 9
    for(int t=0;t<ntile;t++){
        int cur=t&1;
        if(t+1<ntile){
            int k0=(t+1)*BK;
            fa=*(const float4*)(A+(size_t)(m0+mm)*K+k0+kq);
            fb=*(const float4*)(W+(size_t)(n0+mm)*K+k0+kq);
        }
        #pragma unroll
        for(int kk=0;kk<BK;kk++){
            ull av[8], bv[4];
            const float* ar=&As[cur][kk][2*(tr*8)];
            const float* br=&Bs[cur][kk][tc*8];
            #pragma unroll
            for(int p=0;p<4;p++){ ulonglong2 t2=*(const ulonglong2*)(ar+4*p); av[2*p]=t2.x; av[2*p+1]=t2.y; }
            #pragma unroll
            for(int q=0;q<2;q++){ ulonglong2 t2=*(const ulonglong2*)(br+4*q); bv[2*q]=t2.x; bv[2*q+1]=t2.y; }
            #pragma unroll
            for(int i=0;i<8;i++)
                #pragma unroll
                for(int j=0;j<4;j++) fma2(acc[i][j],av[i],bv[j]);
        }
        if(t+1<ntile){
            int nb=cur^1;
            float v[4]={fa.x,fa.y,fa.z,fa.w};
            #pragma unroll
            for(int j=0;j<4;j++) *(ull*)&As[nb][kq+j][2*mm]=pack2(v[j],v[j]);
            Bs[nb][kq+0][mm]=fb.x; Bs[nb][kq+1][mm]=fb.y; Bs[nb][kq+2][mm]=fb.z; Bs[nb][kq+3][mm]=fb.w;
            __syncthreads();
        }
    }

    const int col0=n0+tc*8;
    float4 b0=*(const float4*)(bias+col0);
    float4 b1=*(const float4*)(bias+col0+4);
    #pragma unroll
    for(int i=0;i<8;i++){
        int gm=m0+tr*8+i;
        int b=gm/(Asz*Asz), w=gm%(Asz*Asz);
        int e0=b*Asz+w/Asz, e1=b*Asz+w%Asz;
        const float* pp=PQ+(size_t)e0*(2*Hh)+col0;
        const float* qq=PQ+(size_t)e1*(2*Hh)+Hh+col0;
        float4 p0=*(const float4*)pp, p1=*(const float4*)(pp+4);
        float4 q0=*(const float4*)qq, q1=*(const float4*)(qq+4);
        float v[8];
        #pragma unroll
        for(int j=0;j<4;j++) unpack2(acc[i][j], v[2*j], v[2*j+1]);
        v[0]=siluf(v[0]+b0.x+p0.x+q0.x); v[1]=siluf(v[1]+b0.y+p0.y+q0.y);
        v[2]=siluf(v[2]+b0.z+p0.z+q0.z); v[3]=siluf(v[3]+b0.w+p0.w+q0.w);
        v[4]=siluf(v[4]+b1.x+p1.x+q1.x); v[5]=siluf(v[5]+b1.y+p1.y+q1.y);
        v[6]=siluf(v[6]+b1.z+p1.z+q1.z); v[7]=siluf(v[7]+b1.w+p1.w+q1.w);
        *(float4*)(C+(size_t)gm*Hh+col0)  =make_float4(v[0],v[1],v[2],v[3]);
        *(float4*)(C+(size_t)gm*Hh+col0+4)=make_float4(v[4],v[5],v[6],v[7]);
    }
}

// ===== edge GEMM2 + fused segment-mean: agg[n] = mean_{24} silu(ef1@W2^T+b2)
// 96x128x8, TM=6, TN=8, dup-A static smem (20KB + red alias). No atomics.
__global__ __launch_bounds__(256) void edge2_gemm(
    const float* __restrict__ A,    // ef1 [Ee][256]
    const float* __restrict__ W,    // ew2 [256][256]
    const float* __restrict__ bias, // [256]
    float* __restrict__ agg)        // [Nn][256]
{
    const int BM=96,BN=128,BK=8,K=Hh;
    __shared__ __align__(16) float As[2][BK][2*BM];  // 2*8*192 = 3072 f
    __shared__ __align__(16) float Bs[2][BK][BN];    // 2*8*128 = 2048 f
    float* red = &Bs[0][0][0];                       // alias after mainloop: 16*128 = 2048 f
    const int tid=threadIdx.x;
    const int tc=tid&15, tr=tid>>4;
    const int m0=blockIdx.y*BM, n0=blockIdx.x*BN;
    const int mm=tid>>1, kq=(tid&1)<<2;  // A staging uses tid<192, B staging all 256

    ull acc[6][4];
    #pragma unroll
    for(int i=0;i<6;i++)
        #pragma unroll
        for(int j=0;j<4;j++) acc[i][j]=0ULL;

    float4 fa, fb;
    if(tid<192) fa=*(const float4*)(A+(size_t)(m0+mm)*K+kq);
    fb=*(const float4*)(W+(size_t)(n0+mm)*K+kq);
    {   if(tid<192){
            float v[4]={fa.x,fa.y,fa.z,fa.w};
            #pragma unroll
            for(int j=0;j<4;j++) *(ull*)&As[0][kq+j][2*mm]=pack2(v[j],v[j]);
        }
        Bs[0][kq+0][mm]=fb.x; Bs[0][kq+1][mm]=fb.y; Bs[0][kq+2][mm]=fb.z; Bs[0][kq+3][mm]=fb.w;
    }
    __syncthreads();

    const int ntile=K/BK; // 32
    for(int t=0;t<ntile;t++){
        int cur=t&1;
        if(t+1<ntile){
            int k0=(t+1)*BK;
            if(tid<192) fa=*(const float4*)(A+(size_t)(m0+mm)*K+k0+kq);
            fb=*(const float4*)(W+(size_t)(n0+mm)*K+k0+kq);
        }
        #pragma unroll
        for(int kk=0;kk<BK;kk++){
            ull av[6], bv[4];
            const float* ar=&As[cur][kk][2*(tr*6)];
            const float* br=&Bs[cur][kk][tc*8];
            #pragma unroll
            for(int p=0;p<3;p++){ ulonglong2 t2=*(const ulonglong2*)(ar+4*p); av[2*p]=t2.x; av[2*p+1]=t2.y; }
            #pragma unroll
            for(int q=0;q<2;q++){ ulonglong2 t2=*(const ulonglong2*)(br+4*q); bv[2*q]=t2.x; bv[2*q+1]=t2.y; }
            #pragma unroll
            for(int i=0;i<6;i++)
                #pragma unroll
                for(int j=0;j<4;j++) fma2(acc[i][j],av[i],bv[j]);
        }
        if(t+1<ntile){
            int nb=cur^1;
            if(tid<192){
                float v[4]={fa.x,fa.y,fa.z,fa.w};
                #pragma unroll
                for(int j=0;j<4;j++) *(ull*)&As[nb][kq+j][2*mm]=pack2(v[j],v[j]);
            }
            Bs[nb][kq+0][mm]=fb.x; Bs[nb][kq+1][mm]=fb.y; Bs[nb][kq+2][mm]=fb.z; Bs[nb][kq+3][mm]=fb.w;
            __syncthreads();
        }
    }

    // silu + per-thread partial sums (each thread's 6 rows lie within one node)
    const int col0=tc*8;
    float4 b0=*(const float4*)(bias+n0+col0);
    float4 b1=*(const float4*)(bias+n0+col0+4);
    float cs[8]={0,0,0,0,0,0,0,0};
    #pragma unroll
    for(int i=0;i<6;i++){
        float v[8];
        #pragma unroll
        for(int j=0;j<4;j++) unpack2(acc[i][j], v[2*j], v[2*j+1]);
        cs[0]+=siluf(v[0]+b0.x); cs[1]+=siluf(v[1]+b0.y);
        cs[2]+=siluf(v[2]+b0.z); cs[3]+=siluf(v[3]+b0.w);
        cs[4]+=siluf(v[4]+b1.x); cs[5]+=siluf(v[5]+b1.y);
        cs[6]+=siluf(v[6]+b1.z); cs[7]+=siluf(v[7]+b1.w);
    }
    __syncthreads();   // done with Bs; reuse as red[16][128]
    *(float4*)&red[(size_t)tr*BN+col0]  =make_float4(cs[0],cs[1],cs[2],cs[3]);
    *(float4*)&red[(size_t)tr*BN+col0+4]=make_float4(cs[4],cs[5],cs[6],cs[7]);
    __syncthreads();
    if((tr&3)==0){
        int node = blockIdx.y*4 + (tr>>2);
        #pragma unroll
        for(int q=0;q<2;q++){
            float4 r0=*(const float4*)&red[(size_t)(tr+0)*BN+col0+4*q];
            float4 r1=*(const float4*)&red[(size_t)(tr+1)*BN+col0+4*q];
            float4 r2=*(const float4*)&red[(size_t)(tr+2)*BN+col0+4*q];
            float4 r3=*(const float4*)&red[(size_t)(tr+3)*BN+col0+4*q];
            float4 o=make_float4((r0.x+r1.x+r2.x+r3.x)*(1.f/24.f),
                                 (r0.y+r1.y+r2.y+r3.y)*(1.f/24.f),
                                 (r0.z+r1.z+r2.z+r3.z)*(1.f/24.f),
                                 (r0.w+r1.w+r2.w+r3.w)*(1.f/24.f));
            *(float4*)(agg+(size_t)node*Hh+n0+col0+4*q)=o;
        }
    }
}

// ===== fused: y = nf@w_proj^T + b; nf += silu((LN(y)*fg+fb)*scale + shift) =====
__global__ __launch_bounds__(256) void projfilm(
    const float* __restrict__ wproj, const float* __restrict__ bproj,
    const float* __restrict__ cond,
    const float* __restrict__ fg, const float* __restrict__ fb,
    float* nf)
{
    const int BM=32,BN=256,BK=8,TM=4,TN=8,NT=256,K=Hh;
    __shared__ __align__(16) float As[2][BK][BM];
    __shared__ __align__(16) float Bs[2][BK][BN];
    const int tid=threadIdx.x;
    const int tc=tid%32, tr=tid/32;
    const int m0=blockIdx.x*BM;

    ull acc[TM][TN/2];
    #pragma unroll
    for(int i=0;i<TM;i++)
        #pragma unroll
        for(int j=0;j<TN/2;j++) acc[i][j]=0ULL;

    float ra[1], rb[8];
    { int i=tid; ra[0]=nf[(size_t)(m0+i/BK)*K + i%BK]; }
    #pragma unroll
    for(int u=0;u<8;u++){int i=tid+u*NT; rb[u]=wproj[(size_t)(i/BK)*K + i%BK];}
    { int i=tid; As[0][i%BK][i/BK]=ra[0]; }
    #pragma unroll
    for(int u=0;u<8;u++){int i=tid+u*NT; Bs[0][i%BK][i/BK]=rb[u];}
    __syncthreads();

    const int ntile=K/BK;
    for(int t=0;t<ntile;t++){
        int cur=t&1;
        if(t+1<ntile){
            int k0=(t+1)*BK;
            { int i=tid; ra[0]=nf[(size_t)(m0+i/BK)*K + k0 + i%BK]; }
            #pragma unroll
            for(int u=0;u<8;u++){int i=tid+u*NT; rb[u]=wproj[(size_t)(i/BK)*K + k0 + i%BK];}
        }
        #pragma unroll
        for(int kk=0;kk<BK;kk++){
            ull av[TM], bv[TN/2];
            #pragma unroll
            for(int i=0;i<TM;i++){ float a=As[cur][kk][tr*TM+i]; av[i]=pack2(a,a); }
            #pragma unroll
            for(int j=0;j<TN/2;j++) bv[j]=*reinterpret_cast<const ull*>(&Bs[cur][kk][tc*TN+2*j]);
            #pragma unroll
            for(int i=0;i<TM;i++)
                #pragma unroll
                for(int j=0;j<TN/2;j++) fma2(acc[i][j],av[i],bv[j]);
        }
        if(t+1<ntile){
            int nb=cur^1;
            { int i=tid; As[nb][i%BK][i/BK]=ra[0]; }
            #pragma unroll
            for(int u=0;u<8;u++){int i=tid+u*NT; Bs[nb][i%BK][i/BK]=rb[u];}
            __syncthreads();
        }
    }

    const int col0 = tc*TN;
    #pragma unroll
    for(int i=0;i<TM;i++){
        int gm = m0 + tr*TM + i;
        int g  = gm/Asz;
        float v[8];
        #pragma unroll
        for(int j=0;j<TN/2;j++) unpack2(acc[i][j], v[2*j], v[2*j+1]);
        #pragma unroll
        for(int jj=0;jj<8;jj++) v[jj] += bproj[col0+jj];
        float s=0.f;
        #pragma unroll
        for(int jj=0;jj<8;jj++) s+=v[jj];
        #pragma unroll
        for(int o=16;o>0;o>>=1) s += __shfl_xor_sync(0xffffffffu, s, o);
        float mu = s*(1.0f/256.0f);
        float ss=0.f;
        #pragma unroll
        for(int jj=0;jj<8;jj++){ v[jj]-=mu; ss+=v[jj]*v[jj]; }
        #pragma unroll
        for(int o=16;o>0;o>>=1) ss += __shfl_xor_sync(0xffffffffu, ss, o);
        float rstd = rsqrtf(ss*(1.0f/256.0f) + 1e-5f);
        #pragma unroll
        for(int jj=0;jj<8;jj++){
            int col = col0+jj;
            float y  = v[jj]*rstd*fg[col] + fb[col];
            float sc = cond[(size_t)g*(2*Hh)+col];
            float sh = cond[(size_t)g*(2*Hh)+Hh+col];
            nf[(size_t)gm*Hh+col] += siluf(y*sc + sh);
        }
    }
}

// ================= guarded GEMM (cold paths) ========
template<int BM,int BN,int BK,int TM,int TN,int AMODE>
__global__ void gemm_k(
    int M, int Nout, int K,
    const float* __restrict__ A, int lda,
    const float* __restrict__ A2, int K1, int lda2,
    const float* __restrict__ W, int ldw,
    const float* __restrict__ bias,
    float* __restrict__ C, int ldc,
    int act)
{
    __shared__ float As[BK][BM];
    __shared__ float Bs[BK][BN];
    const int NT = (BM/TM)*(BN/TN);
    const int tid = threadIdx.x;
    const int tc  = tid % (BN/TN);
    const int tr  = tid / (BN/TN);
    const int m0  = blockIdx.y * BM;
    const int n0  = blockIdx.x * BN;

    float acc[TM][TN];
    #pragma unroll
    for (int i=0;i<TM;i++)
        #pragma unroll
        for (int j=0;j<TN;j++) acc[i][j]=0.f;

    for (int k0 = 0; k0 < K; k0 += BK) {
        for (int i = tid; i < BM*BK; i += NT) {
            int mm = i / BK, kk = i % BK;
            int gm = m0 + mm, gk = k0 + kk;
            float v = 0.f;
            if (gm < M && gk < K) {
                if (AMODE == 0) v = A[(size_t)gm*lda + gk];
                else v = (gk < K1) ? A[(size_t)gm*lda + gk] : A2[(size_t)gm*lda2 + (gk-K1)];
            }
            As[kk][mm] = v;
        }
        for (int i = tid; i < BN*BK; i += NT) {
            int nn = i / BK, kk = i % BK;
            int gn = n0 + nn, gk = k0 + kk;
            Bs[kk][nn] = (gn < Nout && gk < K) ? W[(size_t)gn*ldw + gk] : 0.f;
        }
        __syncthreads();
        #pragma unroll
        for (int kk = 0; kk < BK; kk++) {
            float a[TM], b[TN];
            #pragma unroll
            for (int i=0;i<TM;i++) a[i] = As[kk][tr*TM+i];
            #pragma unroll
            for (int j=0;j<TN;j++) b[j] = Bs[kk][tc*TN+j];
            #pragma unroll
            for (int i=0;i<TM;i++)
                #pragma unroll
                for (int j=0;j<TN;j++) acc[i][j] += a[i]*b[j];
        }
        __syncthreads();
    }

    #pragma unroll
    for (int i=0;i<TM;i++) {
        int gm = m0 + tr*TM + i;
        if (gm >= M) continue;
        #pragma unroll
        for (int j=0;j<TN;j++) {
            int gn = n0 + tc*TN + j;
            if (gn >= Nout) continue;
            float v = acc[i][j];
            if (bias) v += bias[gn];
            if (act)  v = siluf(v);
            C[(size_t)gm*ldc + gn] = v;
        }
    }
}

// ---------------- small kernels ----------------
__global__ void copy_f(const float* __restrict__ a, float* __restrict__ b, int n){
    int i=blockIdx.x*blockDim.x+threadIdx.x; if(i<n) b[i]=a[i];
}
__global__ void latips_kernel(const float* __restrict__ L, float* __restrict__ out){
    int idx = blockIdx.x*blockDim.x+threadIdx.x;
    if (idx >= Bsz*9) return;
    int b = idx/9, r = idx%9, i = r/3, k = r%3;
    out[idx] = L[b*9+i*3+0]*L[b*9+k*3+0] + L[b*9+i*3+1]*L[b*9+k*3+1] + L[b*9+i*3+2]*L[b*9+k*3+2];
}
__global__ void latdemb_kernel(const float* __restrict__ fc, const float* __restrict__ latips,
                               float* __restrict__ out){
    int e = blockIdx.x*blockDim.x+threadIdx.x;
    if (e >= Ee) return;
    int b = e/(Asz*Asz), w = e%(Asz*Asz);
    int a = b*Asz + w/Asz, c = b*Asz + w%Asz;
    float* o = out + (size_t)e*LD_PAD;
    #pragma unroll
    for (int i=0;i<9;i++) o[i] = latips[b*9+i];
    #pragma unroll
    for (int d=0;d<3;d++){
        float df = fc[c*3+d] - fc[a*3+d];
        df -= floorf(df);
        #pragma unroll
        for (int f=0;f<NFREQ;f++){
            float ang = 6.283185307179586f * (float)f * df;
            float sn, cs; sincosf(ang, &sn, &cs);
            o[9 + d*NFREQ + f]      = sn;
            o[9 + 30 + d*NFREQ + f] = cs;
        }
    }
    o[69]=0.f; o[70]=0.f; o[71]=0.f;
}
__global__ void pack_w1r(const float* __restrict__ ew1, float* __restrict__ w1r){
    int i = blockIdx.x*blockDim.x+threadIdx.x;
    if (i >= Hh*LD_PAD) return;
    int n = i/LD_PAD, k = i%LD_PAD;
    w1r[i] = (k < 69) ? ew1[(size_t)n*EDGE_IN + 2*Hh + k] : 0.f;
}
__global__ void gfeat2(const float* __restrict__ nf, float* __restrict__ gf){
    int i=blockIdx.x*blockDim.x+threadIdx.x;
    if (i >= Bsz*Hh) return;
    int b=i/Hh, h=i%Hh;
    float s=0.f;
    #pragma unroll
    for(int a=0;a<Asz;a++) s += nf[(size_t)(b*Asz+a)*Hh+h];
    gf[i]=s;
}
__global__ void lattmp_kernel(const float* __restrict__ gf, const float* __restrict__ w_latt,
                              float* __restrict__ lt){
    int idx = blockIdx.x*blockDim.x+threadIdx.x;
    if (idx >= Bsz*9) return;
    int b = idx/9, r = idx%9;
    float s = 0.f;
    for (int k=0;k<Hh;k++) s += gf[b*Hh+k]*w_latt[r*Hh+k];
    lt[idx] = s * (1.f/(float)Asz);
}
__global__ void lattout_kernel(const float* __restrict__ lt, const float* __restrict__ L,
                               float* __restrict__ out){
    int idx = blockIdx.x*blockDim.x+threadIdx.x;
    if (idx >= Bsz*9) return;
    int b = idx/9, r = idx%9, i = r/3, k = r%3;
    float s = 0.f;
    #pragma unroll
    for (int j=0;j<3;j++) s += lt[b*9+i*3+j]*L[b*9+j*3+k];
    out[idx] = s;
}
__global__ void coords_kernel(const float* __restrict__ nf, const float* __restrict__ wc,
                              float* __restrict__ out){
    int idx = blockIdx.x*blockDim.x+threadIdx.x;
    if (idx >= Nn*3) return;
    int n = idx/3, d = idx%3;
    float s = 0.f;
    for (int k=0;k<Hh;k++) s += nf[(size_t)n*Hh+k]*wc[d*Hh+k];
    out[idx] = s;
}

// ---------------- host helpers ----------------
static void gemm_guard(int M,int Nout,int K, const float* A,int lda,
                       const float* W,int ldw, const float* bias,
                       float* C,int ldc,int act){
    dim3 grid((Nout+63)/64, (M+63)/64);
    gemm_k<64,64,16,4,4,0><<<grid,256>>>(M,Nout,K, A,lda, nullptr,0,0,
        W,ldw,bias, C,ldc, act);
}
static void gemm_guard_cat(int M,int Nout,int K1,int K2, const float* A1,const float* A2,
                           const float* W,int ldw,const float* bias,
                           float* C,int ldc,int act){
    dim3 grid((Nout+63)/64, (M+63)/64);
    gemm_k<64,64,16,4,4,1><<<grid,256>>>(M,Nout,K1+K2, A1,K1, A2,K1,K2,
        W,ldw,bias, C,ldc, act);
}

extern "C" void kernel_launch(void* const* d_in, const int* in_sizes, int n_in,
                              void* d_out, int out_size){
    const float* atom_types=(const float*)d_in[0];
    const float* frac      =(const float*)d_in[1];
    const float* lattices  =(const float*)d_in[2];
    const float* t         =(const float*)d_in[3];
    const float* text      =(const float*)d_in[4];
    const float* w_emb     =(const float*)d_in[5];
    const float* b_emb     =(const float*)d_in[6];
    const float* w_cond    =(const float*)d_in[7];
    const float* b_cond    =(const float*)d_in[8];
    const float* w_proj    =(const float*)d_in[9];
    const float* b_proj    =(const float*)d_in[10];
    const float* film_g    =(const float*)d_in[11];
    const float* film_b    =(const float*)d_in[12];
    const float* edge_w1   =(const float*)d_in[13];
    const float* edge_b1   =(const float*)d_in[14];
    const float* edge_w2   =(const float*)d_in[15];
    const float* edge_b2   =(const float*)d_in[16];
    const float* node_w1   =(const float*)d_in[17];
    const float* node_b1   =(const float*)d_in[18];
    const float* node_w2   =(const float*)d_in[19];
    const float* node_b2   =(const float*)d_in[20];
    const float* w_coord   =(const float*)d_in[21];
    const float* w_latt    =(const float*)d_in[22];
    const float* w_type    =(const float*)d_in[23];
    const float* b_type    =(const float*)d_in[24];
    float* out = (float*)d_out;

    float *nf,*PQ,*no1,*agg,*ef1,*ldb,*w1r,*cond,*lips,*gf,*ltmp;
    { void* p;
      cudaGetSymbolAddress(&p, g_nf);      nf   = (float*)p;
      cudaGetSymbolAddress(&p, g_PQ);      PQ   = (float*)p;
      cudaGetSymbolAddress(&p, g_no1);     no1  = (float*)p;
      cudaGetSymbolAddress(&p, g_agg);     agg  = (float*)p;
      cudaGetSymbolAddress(&p, g_ef1);     ef1  = (float*)p;
      cudaGetSymbolAddress(&p, g_latdemb); ldb  = (float*)p;
      cudaGetSymbolAddress(&p, g_w1r);     w1r  = (float*)p;
      cudaGetSymbolAddress(&p, g_cond);    cond = (float*)p;
      cudaGetSymbolAddress(&p, g_latips);  lips = (float*)p;
      cudaGetSymbolAddress(&p, g_gfeat);   gf   = (float*)p;
      cudaGetSymbolAddress(&p, g_lattmp);  ltmp = (float*)p;
    }

    // ----- setup -----
    latips_kernel<<<(Bsz*9+255)/256,256>>>(lattices, lips);
    latdemb_kernel<<<(Ee+255)/256,256>>>(frac, lips, ldb);
    gemm_guard_cat(Bsz, 2*Hh, TIMED, TEXTD, t, text, w_cond, TIMED+TEXTD, b_cond, cond, 2*Hh, 1);
    gemm_guard(Nn, Hh, MAXA, atom_types, MAXA, w_emb, MAXA, b_emb, nf, Hh, 0);

    // ----- layers -----
    for (int i=0;i<NLAYERS;i++){
        const float* ew1 = edge_w1 + (size_t)i*Hh*EDGE_IN;
        const float* eb1 = edge_b1 + i*Hh;
        const float* ew2 = edge_w2 + (size_t)i*Hh*Hh;
        const float* eb2 = edge_b2 + i*Hh;
        const float* nw1 = node_w1 + (size_t)i*Hh*2*Hh;
        const float* nb1 = node_b1 + i*Hh;
        const float* nw2 = node_w2 + (size_t)i*Hh*Hh;
        const float* nb2 = node_b2 + i*Hh;

        // fused proj + LN + FiLM + residual into nf
        projfilm<<<Nn/32,256>>>(w_proj, b_proj, cond, film_g, film_b, nf);

        // pack W1's [lat|demb] slice to padded K=72
        pack_w1r<<<(Hh*LD_PAD+255)/256,256>>>(ew1, w1r);

        // PQ = nf @ [W1a ; W1b]^T  (fused P,Q; Nout=512)
        node_gemm<false,true,false,false><<<dim3(8,48),256>>>(
            nf, nullptr, 0.f, ew1, EDGE_IN, nullptr, nullptr, PQ, 2*Hh, Hh);

        // ef1 = silu(latdemb @ w1r^T + P[e0] + Q[e1] + b1)
        edge1_gemm<<<dim3(2,Ee/128),256>>>(ldb, w1r, eb1, PQ, ef1);

        // agg[n] = mean over node's 24 edges of silu(ef1 @ W2^T + b2)
        edge2_gemm<<<dim3(2,Ee/96),256>>>(ef1, ew2, eb2, agg);

        // no1 = silu([nf, agg] @ nw1^T + nb1)
        node_gemm<true,false,true,false><<<dim3(4,48),256>>>(
            nf, agg, 1.0f, nw1, 2*Hh, nb1, nullptr, no1, Hh, 2*Hh);

        // nf += silu(no1 @ nw2^T + nb2)
        node_gemm<false,false,true,true><<<dim3(4,48),256>>>(
            no1, nullptr, 0.f, nw2, Hh, nb2, nf, nf, Hh, Hh);
    }

    // ----- outputs -----
    gemm_guard(Nn, MAXA, Hh, nf, Hh, w_type, Hh, b_type, out + O_TYPES, MAXA, 0);
    gfeat2<<<(Bsz*Hh+255)/256,256>>>(nf, gf);
    lattmp_kernel<<<(Bsz*9+255)/256,256>>>(gf, w_latt, ltmp);
    lattout_kernel<<<(Bsz*9+255)/256,256>>>(ltmp, lattices, out + O_LATT);
    coords_kernel<<<(Nn*3+255)/256,256>>>(nf, w_coord, out + O_COORD);
    copy_f<<<(Nn*Hh+255)/256,256>>>(nf, out + O_NF, Nn*Hh);
}

// round 11
// speedup vs baseline: 1.8301x; 1.7011x over previous
#include <cuda_runtime.h>
#include <math.h>

// ---------------- problem constants ----------------
#define Hh 256
#define Bsz 128
#define Asz 24
#define Nn (Bsz*Asz)          // 3072 nodes
#define Ee (Bsz*Asz*Asz)      // 73728 edges
#define MAXA 103
#define TIMED 256
#define TEXTD 128
#define NFREQ 10
#define NLAYERS 4
#define DISD (NFREQ*2*3)      // 60
#define EDGE_IN (2*Hh+9+DISD) // 581
#define LD_PAD 72             // 9 lat + 60 demb, padded to 72

// output layout: atom_types_out | lattice_out | coords_out | nf
#define O_TYPES 0
#define O_LATT  (Nn*MAXA)
#define O_COORD (O_LATT + Bsz*9)
#define O_NF    (O_COORD + Nn*3)

typedef unsigned long long ull;

// ---------------- scratch ----------------
__device__ float g_nf[Nn*Hh];
__device__ float g_PQ[Nn*2*Hh];
__device__ float g_no1[Nn*Hh];
__device__ float g_agg[Nn*Hh];
__device__ float g_ef1[(size_t)Ee*Hh];
__device__ float g_latdemb[(size_t)Ee*LD_PAD];
__device__ float g_w1r[Hh*LD_PAD];
__device__ float g_cond[Bsz*2*Hh];
__device__ float g_latips[Bsz*9];
__device__ float g_gfeat[Bsz*Hh];
__device__ float g_lattmp[Bsz*9];

__device__ __forceinline__ float siluf(float x){ return x / (1.f + expf(-x)); }

__device__ __forceinline__ ull pack2(float x, float y){
    ull r; asm("mov.b64 %0, {%1, %2};" : "=l"(r) : "f"(x), "f"(y)); return r;
}
__device__ __forceinline__ void unpack2(ull v, float &x, float &y){
    asm("mov.b64 {%0, %1}, %2;" : "=f"(x), "=f"(y) : "l"(v));
}
__device__ __forceinline__ void fma2(ull &d, ull a, ull b){
    asm("fma.rn.f32x2 %0, %1, %2, %0;" : "+l"(d) : "l"(a), "l"(b));
}

// ================= fast node GEMM: 64x64x8, TM=TN=4, f32x2 =================
// B smem: [BK][16 groups][6] pad -> lane stride 6 floats, (6*tc+2j)%32 distinct
template<bool CONCAT,bool WSPLIT,bool ACT,bool RESID>
__global__ __launch_bounds__(256) void node_gemm(
    const float* __restrict__ A,
    const float* __restrict__ A2, float s2,
    const float* __restrict__ W, int ldw,
    const float* __restrict__ bias,
    const float* resid,
    float* C, int Nout, int K)
{
    const int BM=64,BN=64,BK=8,TM=4,TN=4,NT=256;
    __shared__ __align__(16) float As[2][BK][BM];
    __shared__ __align__(16) float Bs2[2][BK][16][6];
    const int tid=threadIdx.x;
    const int tc=tid%(BN/TN), tr=tid/(BN/TN);
    const int m0=blockIdx.y*BM, n0=blockIdx.x*BN;

    ull acc[TM][TN/2];
    #pragma unroll
    for(int i=0;i<TM;i++)
        #pragma unroll
        for(int j=0;j<TN/2;j++) acc[i][j]=0ULL;

    float ra[2], rb[2];
    #pragma unroll
    for(int u=0;u<2;u++){
        int i=tid+u*NT; int mm=i/BK, kk=i%BK;
        int gm=m0+mm, gk=kk;
        if(CONCAT) ra[u] = (gk<Hh)? A[(size_t)gm*Hh+gk] : A2[(size_t)gm*Hh+gk-Hh]*s2;
        else       ra[u] = A[(size_t)gm*K+gk];
    }
    #pragma unroll
    for(int u=0;u<2;u++){
        int i=tid+u*NT; int nn=i/BK, kk=i%BK;
        int gn=n0+nn, gk=kk;
        if(WSPLIT) rb[u] = (gn<Hh)? W[(size_t)gn*ldw+gk] : W[(size_t)(gn-Hh)*ldw+Hh+gk];
        else       rb[u] = W[(size_t)gn*ldw+gk];
    }
    #pragma unroll
    for(int u=0;u<2;u++){int i=tid+u*NT; As[0][i%BK][i/BK]=ra[u];}
    #pragma unroll
    for(int u=0;u<2;u++){int i=tid+u*NT; int nn=i/BK; Bs2[0][i%BK][nn>>2][nn&3]=rb[u];}
    __syncthreads();

    const int ntile=K/BK;
    for(int t=0;t<ntile;t++){
        int cur=t&1;
        if(t+1<ntile){
            int k0=(t+1)*BK;
            #pragma unroll
            for(int u=0;u<2;u++){
                int i=tid+u*NT; int mm=i/BK, kk=i%BK;
                int gm=m0+mm, gk=k0+kk;
                if(CONCAT) ra[u] = (gk<Hh)? A[(size_t)gm*Hh+gk] : A2[(size_t)gm*Hh+gk-Hh]*s2;
                else       ra[u] = A[(size_t)gm*K+gk];
            }
            #pragma unroll
            for(int u=0;u<2;u++){
                int i=tid+u*NT; int nn=i/BK, kk=i%BK;
                int gn=n0+nn, gk=k0+kk;
                if(WSPLIT) rb[u] = (gn<Hh)? W[(size_t)gn*ldw+gk] : W[(size_t)(gn-Hh)*ldw+Hh+gk];
                else       rb[u] = W[(size_t)gn*ldw+gk];
            }
        }
        #pragma unroll
        for(int kk=0;kk<BK;kk++){
            ull av[TM], bv[TN/2];
            #pragma unroll
            for(int i=0;i<TM;i++){ float a=As[cur][kk][tr*TM+i]; av[i]=pack2(a,a); }
            #pragma unroll
            for(int j=0;j<TN/2;j++) bv[j]=*reinterpret_cast<const ull*>(&Bs2[cur][kk][tc][2*j]);
            #pragma unroll
            for(int i=0;i<TM;i++)
                #pragma unroll
                for(int j=0;j<TN/2;j++) fma2(acc[i][j],av[i],bv[j]);
        }
        if(t+1<ntile){
            int nb=cur^1;
            #pragma unroll
            for(int u=0;u<2;u++){int i=tid+u*NT; As[nb][i%BK][i/BK]=ra[u];}
            #pragma unroll
            for(int u=0;u<2;u++){int i=tid+u*NT; int nn=i/BK; Bs2[nb][i%BK][nn>>2][nn&3]=rb[u];}
            __syncthreads();
        }
    }

    #pragma unroll
    for(int i=0;i<TM;i++){
        int gm=m0+tr*TM+i;
        #pragma unroll
        for(int j=0;j<TN/2;j++){
            float v0,v1; unpack2(acc[i][j],v0,v1);
            int col=n0+tc*TN+2*j;
            if(bias){ v0+=bias[col]; v1+=bias[col+1]; }
            if(ACT){ v0=siluf(v0); v1=siluf(v1); }
            if(RESID){ v0+=resid[(size_t)gm*Nout+col]; v1+=resid[(size_t)gm*Nout+col+1]; }
            C[(size_t)gm*Nout+col]=v0; C[(size_t)gm*Nout+col+1]=v1;
        }
    }
}

// ================= edge GEMM1: ef1 = silu(latdemb@W1r^T + P[e0]+Q[e1]+b1) ====
// 128x128x8, TM=TN=8, K=72. B smem: [BK][16][10] pad -> (10*tc+2j)%32 distinct.
__global__ __launch_bounds__(256) void edge1_gemm(
    const float* __restrict__ A,    // [Ee][72]
    const float* __restrict__ W,    // [256][72] packed
    const float* __restrict__ bias, // [256]
    const float* __restrict__ PQ,   // [Nn][512]
    float* __restrict__ C)          // [Ee][256]
{
    const int BM=128,BN=128,BK=8,TM=8,TN=8,NT=256,K=LD_PAD;
    __shared__ __align__(16) float As[2][BK][BM];
    __shared__ __align__(16) float Bs2[2][BK][16][10];
    const int tid=threadIdx.x;
    const int tc=tid%(BN/TN), tr=tid/(BN/TN);
    const int m0=blockIdx.y*BM, n0=blockIdx.x*BN;

    ull acc[TM][TN/2];
    #pragma unroll
    for(int i=0;i<TM;i++)
        #pragma unroll
        for(int j=0;j<TN/2;j++) acc[i][j]=0ULL;

    float ra[4], rb[4];
    #pragma unroll
    for(int u=0;u<4;u++){int i=tid+u*NT; ra[u]=A[(size_t)(m0+i/BK)*K + i%BK];}
    #pragma unroll
    for(int u=0;u<4;u++){int i=tid+u*NT; rb[u]=W[(size_t)(n0+i/BK)*K + i%BK];}
    #pragma unroll
    for(int u=0;u<4;u++){int i=tid+u*NT; As[0][i%BK][i/BK]=ra[u];}
    #pragma unroll
    for(int u=0;u<4;u++){int i=tid+u*NT; int nn=i/BK; Bs2[0][i%BK][nn>>3][nn&7]=rb[u];}
    __syncthreads();

    const int ntile=K/BK; // 9
    for(int t=0;t<ntile;t++){
        int cur=t&1;
        if(t+1<ntile){
            int k0=(t+1)*BK;
            #pragma unroll
            for(int u=0;u<4;u++){int i=tid+u*NT; ra[u]=A[(size_t)(m0+i/BK)*K + k0 + i%BK];}
            #pragma unroll
            for(int u=0;u<4;u++){int i=tid+u*NT; rb[u]=W[(size_t)(n0+i/BK)*K + k0 + i%BK];}
        }
        #pragma unroll
        for(int kk=0;kk<BK;kk++){
            ull av[TM], bv[TN/2];
            #pragma unroll
            for(int i=0;i<TM;i++){ float a=As[cur][kk][tr*TM+i]; av[i]=pack2(a,a); }
            #pragma unroll
            for(int j=0;j<TN/2;j++) bv[j]=*reinterpret_cast<const ull*>(&Bs2[cur][kk][tc][2*j]);
            #pragma unroll
            for(int i=0;i<TM;i++)
                #pragma unroll
                for(int j=0;j<TN/2;j++) fma2(acc[i][j],av[i],bv[j]);
        }
        if(t+1<ntile){
            int nb=cur^1;
            #pragma unroll
            for(int u=0;u<4;u++){int i=tid+u*NT; As[nb][i%BK][i/BK]=ra[u];}
            #pragma unroll
            for(int u=0;u<4;u++){int i=tid+u*NT; int nn=i/BK; Bs2[nb][i%BK][nn>>3][nn&7]=rb[u];}
            __syncthreads();
        }
    }

    const int col0 = n0 + tc*TN;
    const float4 b4a = *(const float4*)(bias+col0);
    const float4 b4b = *(const float4*)(bias+col0+4);
    #pragma unroll
    for(int i=0;i<TM;i++){
        int gm=m0+tr*TM+i;
        int b  = gm/(Asz*Asz), w = gm%(Asz*Asz);
        int e0 = b*Asz + w/Asz, e1 = b*Asz + w%Asz;
        const float4* pp=(const float4*)(PQ + (size_t)e0*(2*Hh) + col0);
        const float4* qq=(const float4*)(PQ + (size_t)e1*(2*Hh) + Hh + col0);
        float4 pa=pp[0], pb=pp[1], qa=qq[0], qb=qq[1];
        float v[8];
        #pragma unroll
        for(int j=0;j<TN/2;j++) unpack2(acc[i][j], v[2*j], v[2*j+1]);
        v[0]=siluf(v[0]+b4a.x+pa.x+qa.x); v[1]=siluf(v[1]+b4a.y+pa.y+qa.y);
        v[2]=siluf(v[2]+b4a.z+pa.z+qa.z); v[3]=siluf(v[3]+b4a.w+pa.w+qa.w);
        v[4]=siluf(v[4]+b4b.x+pb.x+qb.x); v[5]=siluf(v[5]+b4b.y+pb.y+qb.y);
        v[6]=siluf(v[6]+b4b.z+pb.z+qb.z); v[7]=siluf(v[7]+b4b.w+pb.w+qb.w);
        float4* o=(float4*)(C + (size_t)gm*Hh + col0);
        o[0]=make_float4(v[0],v[1],v[2],v[3]);
        o[1]=make_float4(v[4],v[5],v[6],v[7]);
    }
}

// ===== edge GEMM2 + fused segment-mean: agg[n] = mean_{24 edges} silu(ef1@W2^T+b2)
// 96x128x8, TM=6, TN=8. B smem padded [BK][16][10]. No atomics.
__global__ __launch_bounds__(256) void edge2_gemm(
    const float* __restrict__ A,    // ef1 [Ee][256]
    const float* __restrict__ W,    // ew2 [256][256]
    const float* __restrict__ bias, // [256]
    float* __restrict__ agg)        // [Nn][256]
{
    const int BM=96,BN=128,BK=8,TM=6,TN=8,NT=256,K=Hh;
    __shared__ __align__(16) float As[2][BK][BM];
    __shared__ __align__(16) float Bs2[2][BK][16][10];
    __shared__ float red[16][BN];
    const int tid=threadIdx.x;
    const int tc=tid%(BN/TN), tr=tid/(BN/TN);
    const int m0=blockIdx.y*BM, n0=blockIdx.x*BN;

    ull acc[TM][TN/2];
    #pragma unroll
    for(int i=0;i<TM;i++)
        #pragma unroll
        for(int j=0;j<TN/2;j++) acc[i][j]=0ULL;

    float ra[3], rb[4];
    #pragma unroll
    for(int u=0;u<3;u++){int i=tid+u*NT; ra[u]=A[(size_t)(m0+i/BK)*K + i%BK];}
    #pragma unroll
    for(int u=0;u<4;u++){int i=tid+u*NT; rb[u]=W[(size_t)(n0+i/BK)*K + i%BK];}
    #pragma unroll
    for(int u=0;u<3;u++){int i=tid+u*NT; As[0][i%BK][i/BK]=ra[u];}
    #pragma unroll
    for(int u=0;u<4;u++){int i=tid+u*NT; int nn=i/BK; Bs2[0][i%BK][nn>>3][nn&7]=rb[u];}
    __syncthreads();

    const int ntile=K/BK; // 32
    for(int t=0;t<ntile;t++){
        int cur=t&1;
        if(t+1<ntile){
            int k0=(t+1)*BK;
            #pragma unroll
            for(int u=0;u<3;u++){int i=tid+u*NT; ra[u]=A[(size_t)(m0+i/BK)*K + k0 + i%BK];}
            #pragma unroll
            for(int u=0;u<4;u++){int i=tid+u*NT; rb[u]=W[(size_t)(n0+i/BK)*K + k0 + i%BK];}
        }
        #pragma unroll
        for(int kk=0;kk<BK;kk++){
            ull av[TM], bv[TN/2];
            #pragma unroll
            for(int i=0;i<TM;i++){ float a=As[cur][kk][tr*TM+i]; av[i]=pack2(a,a); }
            #pragma unroll
            for(int j=0;j<TN/2;j++) bv[j]=*reinterpret_cast<const ull*>(&Bs2[cur][kk][tc][2*j]);
            #pragma unroll
            for(int i=0;i<TM;i++)
                #pragma unroll
                for(int j=0;j<TN/2;j++) fma2(acc[i][j],av[i],bv[j]);
        }
        if(t+1<ntile){
            int nb=cur^1;
            #pragma unroll
            for(int u=0;u<3;u++){int i=tid+u*NT; As[nb][i%BK][i/BK]=ra[u];}
            #pragma unroll
            for(int u=0;u<4;u++){int i=tid+u*NT; int nn=i/BK; Bs2[nb][i%BK][nn>>3][nn&7]=rb[u];}
            __syncthreads();
        }
    }

    // silu + per-thread row-group partial sum (each thread's 6 rows are in one node)
    const int col0 = n0 + tc*TN;
    float colsum[8] = {0,0,0,0,0,0,0,0};
    #pragma unroll
    for(int i=0;i<TM;i++){
        #pragma unroll
        for(int j=0;j<TN/2;j++){
            float v0,v1; unpack2(acc[i][j],v0,v1);
            colsum[2*j]   += siluf(v0 + bias[col0+2*j]);
            colsum[2*j+1] += siluf(v1 + bias[col0+2*j+1]);
        }
    }
    __syncthreads();
    #pragma unroll
    for(int jj=0;jj<8;jj++) red[tr][tc*TN+jj]=colsum[jj];
    __syncthreads();
    if((tr&3)==0){
        int node = m0/Asz + (tr>>2);
        #pragma unroll
        for(int jj=0;jj<8;jj++){
            int c = tc*TN+jj;
            float s = red[tr][c]+red[tr+1][c]+red[tr+2][c]+red[tr+3][c];
            agg[(size_t)node*Hh + n0 + c] = s*(1.0f/24.0f);
        }
    }
}

// ===== fused: y = nf@w_proj^T + b; nf += silu((LN(y)*fg+fb)*scale + shift) =====
// B smem: [BK][32][10] pad; tc stride 10 floats.
__global__ __launch_bounds__(256) void projfilm(
    const float* __restrict__ wproj, const float* __restrict__ bproj,
    const float* __restrict__ cond,  // [B][512]
    const float* __restrict__ fg, const float* __restrict__ fb,
    float* nf)
{
    const int BM=32,BN=256,BK=8,TM=4,TN=8,NT=256,K=Hh;
    __shared__ __align__(16) float As[2][BK][BM];
    __shared__ __align__(16) float Bs2[2][BK][32][10];
    const int tid=threadIdx.x;
    const int tc=tid%32, tr=tid/32;     // warp == fixed tr
    const int m0=blockIdx.x*BM;

    ull acc[TM][TN/2];
    #pragma unroll
    for(int i=0;i<TM;i++)
        #pragma unroll
        for(int j=0;j<TN/2;j++) acc[i][j]=0ULL;

    float ra[1], rb[8];
    { int i=tid; ra[0]=nf[(size_t)(m0+i/BK)*K + i%BK]; }
    #pragma unroll
    for(int u=0;u<8;u++){int i=tid+u*NT; rb[u]=wproj[(size_t)(i/BK)*K + i%BK];}
    { int i=tid; As[0][i%BK][i/BK]=ra[0]; }
    #pragma unroll
    for(int u=0;u<8;u++){int i=tid+u*NT; int nn=i/BK; Bs2[0][i%BK][nn>>3][nn&7]=rb[u];}
    __syncthreads();

    const int ntile=K/BK;
    for(int t=0;t<ntile;t++){
        int cur=t&1;
        if(t+1<ntile){
            int k0=(t+1)*BK;
            { int i=tid; ra[0]=nf[(size_t)(m0+i/BK)*K + k0 + i%BK]; }
            #pragma unroll
            for(int u=0;u<8;u++){int i=tid+u*NT; rb[u]=wproj[(size_t)(i/BK)*K + k0 + i%BK];}
        }
        #pragma unroll
        for(int kk=0;kk<BK;kk++){
            ull av[TM], bv[TN/2];
            #pragma unroll
            for(int i=0;i<TM;i++){ float a=As[cur][kk][tr*TM+i]; av[i]=pack2(a,a); }
            #pragma unroll
            for(int j=0;j<TN/2;j++) bv[j]=*reinterpret_cast<const ull*>(&Bs2[cur][kk][tc][2*j]);
            #pragma unroll
            for(int i=0;i<TM;i++)
                #pragma unroll
                for(int j=0;j<TN/2;j++) fma2(acc[i][j],av[i],bv[j]);
        }
        if(t+1<ntile){
            int nb=cur^1;
            { int i=tid; As[nb][i%BK][i/BK]=ra[0]; }
            #pragma unroll
            for(int u=0;u<8;u++){int i=tid+u*NT; int nn=i/BK; Bs2[nb][i%BK][nn>>3][nn&7]=rb[u];}
            __syncthreads();
        }
    }

    const int col0 = tc*TN;
    #pragma unroll
    for(int i=0;i<TM;i++){
        int gm = m0 + tr*TM + i;
        int g  = gm/Asz;
        float v[8];
        #pragma unroll
        for(int j=0;j<TN/2;j++) unpack2(acc[i][j], v[2*j], v[2*j+1]);
        #pragma unroll
        for(int jj=0;jj<8;jj++) v[jj] += bproj[col0+jj];
        float s=0.f;
        #pragma unroll
        for(int jj=0;jj<8;jj++) s+=v[jj];
        #pragma unroll
        for(int o=16;o>0;o>>=1) s += __shfl_xor_sync(0xffffffffu, s, o);
        float mu = s*(1.0f/256.0f);
        float ss=0.f;
        #pragma unroll
        for(int jj=0;jj<8;jj++){ v[jj]-=mu; ss+=v[jj]*v[jj]; }
        #pragma unroll
        for(int o=16;o>0;o>>=1) ss += __shfl_xor_sync(0xffffffffu, ss, o);
        float rstd = rsqrtf(ss*(1.0f/256.0f) + 1e-5f);
        #pragma unroll
        for(int jj=0;jj<8;jj++){
            int col = col0+jj;
            float y  = v[jj]*rstd*fg[col] + fb[col];
            float sc = cond[(size_t)g*(2*Hh)+col];
            float sh = cond[(size_t)g*(2*Hh)+Hh+col];
            nf[(size_t)gm*Hh+col] += siluf(y*sc + sh);
        }
    }
}

// ================= old guarded GEMM (cold paths: cond, embed, types) ========
template<int BM,int BN,int BK,int TM,int TN,int AMODE>
__global__ void gemm_k(
    int M, int Nout, int K,
    const float* __restrict__ A, int lda,
    const float* __restrict__ A2, int K1, int lda2,
    const float* __restrict__ W, int ldw,
    const float* __restrict__ bias,
    float* __restrict__ C, int ldc,
    int act)
{
    __shared__ float As[BK][BM];
    __shared__ float Bs[BK][BN];
    const int NT = (BM/TM)*(BN/TN);
    const int tid = threadIdx.x;
    const int tc  = tid % (BN/TN);
    const int tr  = tid / (BN/TN);
    const int m0  = blockIdx.y * BM;
    const int n0  = blockIdx.x * BN;

    float acc[TM][TN];
    #pragma unroll
    for (int i=0;i<TM;i++)
        #pragma unroll
        for (int j=0;j<TN;j++) acc[i][j]=0.f;

    for (int k0 = 0; k0 < K; k0 += BK) {
        for (int i = tid; i < BM*BK; i += NT) {
            int mm = i / BK, kk = i % BK;
            int gm = m0 + mm, gk = k0 + kk;
            float v = 0.f;
            if (gm < M && gk < K) {
                if (AMODE == 0) v = A[(size_t)gm*lda + gk];
                else v = (gk < K1) ? A[(size_t)gm*lda + gk] : A2[(size_t)gm*lda2 + (gk-K1)];
            }
            As[kk][mm] = v;
        }
        for (int i = tid; i < BN*BK; i += NT) {
            int nn = i / BK, kk = i % BK;
            int gn = n0 + nn, gk = k0 + kk;
            Bs[kk][nn] = (gn < Nout && gk < K) ? W[(size_t)gn*ldw + gk] : 0.f;
        }
        __syncthreads();
        #pragma unroll
        for (int kk = 0; kk < BK; kk++) {
            float a[TM], b[TN];
            #pragma unroll
            for (int i=0;i<TM;i++) a[i] = As[kk][tr*TM+i];
            #pragma unroll
            for (int j=0;j<TN;j++) b[j] = Bs[kk][tc*TN+j];
            #pragma unroll
            for (int i=0;i<TM;i++)
                #pragma unroll
                for (int j=0;j<TN;j++) acc[i][j] += a[i]*b[j];
        }
        __syncthreads();
    }

    #pragma unroll
    for (int i=0;i<TM;i++) {
        int gm = m0 + tr*TM + i;
        if (gm >= M) continue;
        #pragma unroll
        for (int j=0;j<TN;j++) {
            int gn = n0 + tc*TN + j;
            if (gn >= Nout) continue;
            float v = acc[i][j];
            if (bias) v += bias[gn];
            if (act)  v = siluf(v);
            C[(size_t)gm*ldc + gn] = v;
        }
    }
}

// ---------------- small kernels ----------------
__global__ void copy_f(const float* __restrict__ a, float* __restrict__ b, int n){
    int i=blockIdx.x*blockDim.x+threadIdx.x; if(i<n) b[i]=a[i];
}
__global__ void latips_kernel(const float* __restrict__ L, float* __restrict__ out){
    int idx = blockIdx.x*blockDim.x+threadIdx.x;
    if (idx >= Bsz*9) return;
    int b = idx/9, r = idx%9, i = r/3, k = r%3;
    out[idx] = L[b*9+i*3+0]*L[b*9+k*3+0] + L[b*9+i*3+1]*L[b*9+k*3+1] + L[b*9+i*3+2]*L[b*9+k*3+2];
}
__global__ void latdemb_kernel(const float* __restrict__ fc, const float* __restrict__ latips,
                               float* __restrict__ out){
    int e = blockIdx.x*blockDim.x+threadIdx.x;
    if (e >= Ee) return;
    int b = e/(Asz*Asz), w = e%(Asz*Asz);
    int a = b*Asz + w/Asz, c = b*Asz + w%Asz;
    float* o = out + (size_t)e*LD_PAD;
    #pragma unroll
    for (int i=0;i<9;i++) o[i] = latips[b*9+i];
    #pragma unroll
    for (int d=0;d<3;d++){
        float df = fc[c*3+d] - fc[a*3+d];
        df -= floorf(df);
        #pragma unroll
        for (int f=0;f<NFREQ;f++){
            float ang = 6.283185307179586f * (float)f * df;
            float sn, cs; sincosf(ang, &sn, &cs);
            o[9 + d*NFREQ + f]      = sn;
            o[9 + 30 + d*NFREQ + f] = cs;
        }
    }
    o[69]=0.f; o[70]=0.f; o[71]=0.f;
}
__global__ void pack_w1r(const float* __restrict__ ew1, float* __restrict__ w1r){
    int i = blockIdx.x*blockDim.x+threadIdx.x;
    if (i >= Hh*LD_PAD) return;
    int n = i/LD_PAD, k = i%LD_PAD;
    w1r[i] = (k < 69) ? ew1[(size_t)n*EDGE_IN + 2*Hh + k] : 0.f;
}
__global__ void gfeat2(const float* __restrict__ nf, float* __restrict__ gf){
    int i=blockIdx.x*blockDim.x+threadIdx.x;
    if (i >= Bsz*Hh) return;
    int b=i/Hh, h=i%Hh;
    float s=0.f;
    #pragma unroll
    for(int a=0;a<Asz;a++) s += nf[(size_t)(b*Asz+a)*Hh+h];
    gf[i]=s;
}
__global__ void lattmp_kernel(const float* __restrict__ gf, const float* __restrict__ w_latt,
                              float* __restrict__ lt){
    int idx = blockIdx.x*blockDim.x+threadIdx.x;
    if (idx >= Bsz*9) return;
    int b = idx/9, r = idx%9;
    float s = 0.f;
    for (int k=0;k<Hh;k++) s += gf[b*Hh+k]*w_latt[r*Hh+k];
    lt[idx] = s * (1.f/(float)Asz);
}
__global__ void lattout_kernel(const float* __restrict__ lt, const float* __restrict__ L,
                               float* __restrict__ out){
    int idx = blockIdx.x*blockDim.x+threadIdx.x;
    if (idx >= Bsz*9) return;
    int b = idx/9, r = idx%9, i = r/3, k = r%3;
    float s = 0.f;
    #pragma unroll
    for (int j=0;j<3;j++) s += lt[b*9+i*3+j]*L[b*9+j*3+k];
    out[idx] = s;
}
__global__ void coords_kernel(const float* __restrict__ nf, const float* __restrict__ wc,
                              float* __restrict__ out){
    int idx = blockIdx.x*blockDim.x+threadIdx.x;
    if (idx >= Nn*3) return;
    int n = idx/3, d = idx%3;
    float s = 0.f;
    for (int k=0;k<Hh;k++) s += nf[(size_t)n*Hh+k]*wc[d*Hh+k];
    out[idx] = s;
}

// ---------------- host-side launch helpers ----------------
static void gemm_guard(int M,int Nout,int K, const float* A,int lda,
                       const float* W,int ldw, const float* bias,
                       float* C,int ldc,int act){
    dim3 grid((Nout+63)/64, (M+63)/64);
    gemm_k<64,64,16,4,4,0><<<grid,256>>>(M,Nout,K, A,lda, nullptr,0,0,
        W,ldw,bias, C,ldc, act);
}
static void gemm_guard_cat(int M,int Nout,int K1,int K2, const float* A1,const float* A2,
                           const float* W,int ldw,const float* bias,
                           float* C,int ldc,int act){
    dim3 grid((Nout+63)/64, (M+63)/64);
    gemm_k<64,64,16,4,4,1><<<grid,256>>>(M,Nout,K1+K2, A1,K1, A2,K1,K2,
        W,ldw,bias, C,ldc, act);
}

extern "C" void kernel_launch(void* const* d_in, const int* in_sizes, int n_in,
                              void* d_out, int out_size){
    const float* atom_types=(const float*)d_in[0];
    const float* frac      =(const float*)d_in[1];
    const float* lattices  =(const float*)d_in[2];
    const float* t         =(const float*)d_in[3];
    const float* text      =(const float*)d_in[4];
    const float* w_emb     =(const float*)d_in[5];
    const float* b_emb     =(const float*)d_in[6];
    const float* w_cond    =(const float*)d_in[7];
    const float* b_cond    =(const float*)d_in[8];
    const float* w_proj    =(const float*)d_in[9];
    const float* b_proj    =(const float*)d_in[10];
    const float* film_g    =(const float*)d_in[11];
    const float* film_b    =(const float*)d_in[12];
    const float* edge_w1   =(const float*)d_in[13];
    const float* edge_b1   =(const float*)d_in[14];
    const float* edge_w2   =(const float*)d_in[15];
    const float* edge_b2   =(const float*)d_in[16];
    const float* node_w1   =(const float*)d_in[17];
    const float* node_b1   =(const float*)d_in[18];
    const float* node_w2   =(const float*)d_in[19];
    const float* node_b2   =(const float*)d_in[20];
    const float* w_coord   =(const float*)d_in[21];
    const float* w_latt    =(const float*)d_in[22];
    const float* w_type    =(const float*)d_in[23];
    const float* b_type    =(const float*)d_in[24];
    float* out = (float*)d_out;

    float *nf,*PQ,*no1,*agg,*ef1,*ldb,*w1r,*cond,*lips,*gf,*ltmp;
    { void* p;
      cudaGetSymbolAddress(&p, g_nf);      nf   = (float*)p;
      cudaGetSymbolAddress(&p, g_PQ);      PQ   = (float*)p;
      cudaGetSymbolAddress(&p, g_no1);     no1  = (float*)p;
      cudaGetSymbolAddress(&p, g_agg);     agg  = (float*)p;
      cudaGetSymbolAddress(&p, g_ef1);     ef1  = (float*)p;
      cudaGetSymbolAddress(&p, g_latdemb); ldb  = (float*)p;
      cudaGetSymbolAddress(&p, g_w1r);     w1r  = (float*)p;
      cudaGetSymbolAddress(&p, g_cond);    cond = (float*)p;
      cudaGetSymbolAddress(&p, g_latips);  lips = (float*)p;
      cudaGetSymbolAddress(&p, g_gfeat);   gf   = (float*)p;
      cudaGetSymbolAddress(&p, g_lattmp);  ltmp = (float*)p;
    }

    // ----- setup -----
    latips_kernel<<<(Bsz*9+255)/256,256>>>(lattices, lips);
    latdemb_kernel<<<(Ee+255)/256,256>>>(frac, lips, ldb);
    gemm_guard_cat(Bsz, 2*Hh, TIMED, TEXTD, t, text, w_cond, TIMED+TEXTD, b_cond, cond, 2*Hh, 1);
    gemm_guard(Nn, Hh, MAXA, atom_types, MAXA, w_emb, MAXA, b_emb, nf, Hh, 0);

    // ----- layers -----
    for (int i=0;i<NLAYERS;i++){
        const float* ew1 = edge_w1 + (size_t)i*Hh*EDGE_IN;
        const float* eb1 = edge_b1 + i*Hh;
        const float* ew2 = edge_w2 + (size_t)i*Hh*Hh;
        const float* eb2 = edge_b2 + i*Hh;
        const float* nw1 = node_w1 + (size_t)i*Hh*2*Hh;
        const float* nb1 = node_b1 + i*Hh;
        const float* nw2 = node_w2 + (size_t)i*Hh*Hh;
        const float* nb2 = node_b2 + i*Hh;

        // fused proj + LN + FiLM + residual into nf
        projfilm<<<Nn/32,256>>>(w_proj, b_proj, cond, film_g, film_b, nf);

        // pack W1's [lat|demb] slice to padded K=72
        pack_w1r<<<(Hh*LD_PAD+255)/256,256>>>(ew1, w1r);

        // PQ = nf @ [W1a ; W1b]^T  (fused P,Q; Nout=512)
        node_gemm<false,true,false,false><<<dim3(8,48),256>>>(
            nf, nullptr, 0.f, ew1, EDGE_IN, nullptr, nullptr, PQ, 2*Hh, Hh);

        // ef1 = silu(latdemb @ W1r^T + P[e0] + Q[e1] + b1)
        edge1_gemm<<<dim3(2,576),256>>>(ldb, w1r, eb1, PQ, ef1);

        // agg[n] = mean over node's 24 edges of silu(ef1 @ W2^T + b2)
        edge2_gemm<<<dim3(2,768),256>>>(ef1, ew2, eb2, agg);

        // no1 = silu([nf, agg] @ nw1^T + nb1)   (agg already divided by deg)
        node_gemm<true,false,true,false><<<dim3(4,48),256>>>(
            nf, agg, 1.0f, nw1, 2*Hh, nb1, nullptr, no1, Hh, 2*Hh);

        // nf += silu(no1 @ nw2^T + nb2)
        node_gemm<false,false,true,true><<<dim3(4,48),256>>>(
            no1, nullptr, 0.f, nw2, Hh, nb2, nf, nf, Hh, Hh);
    }

    // ----- outputs -----
    gemm_guard(Nn, MAXA, Hh, nf, Hh, w_type, Hh, b_type, out + O_TYPES, MAXA, 0);
    gfeat2<<<(Bsz*Hh+255)/256,256>>>(nf, gf);
    lattmp_kernel<<<(Bsz*9+255)/256,256>>>(gf, w_latt, ltmp);
    lattout_kernel<<<(Bsz*9+255)/256,256>>>(ltmp, lattices, out + O_LATT);
    coords_kernel<<<(Nn*3+255)/256,256>>>(nf, w_coord, out + O_COORD);
    copy_f<<<(Nn*Hh+255)/256,256>>>(nf, out + O_NF, Nn*Hh);
}